// round 1
// baseline (speedup 1.0000x reference)
#include <cuda_runtime.h>
#include <math.h>
#include <stdint.h>

// ---------------- problem constants ----------------
#define M_NODES 20000
#define D_NODES 8000
#define E_MM    320000
#define E_DD    128000
#define MAXN    20000
#define MAXHC   256
#define MAXH    2
#define MAXE    320000

// ---------------- scratch (device globals; allocation-free) ----------------
__device__ float    g_h   [MAXN * MAXHC];   // h = x @ W for current GAT layer
__device__ float    g_feat[MAXN * MAXHC];   // layer-1 GAT output (post relu)
__device__ float    g_agg [MAXN * MAXHC];   // scatter accumulation
__device__ float    g_asrc[MAXN * MAXH];
__device__ float    g_adst[MAXN * MAXH];
__device__ unsigned g_emax[MAXN * MAXH];
__device__ float    g_den [MAXN * MAXH];
__device__ float    g_ee  [MAXE * MAXH];    // per-edge logits / exp values
__device__ float    g_X   [MAXN * 64];      // GAT-2 output (x or y features)
__device__ float    g_t1  [MAXN * 256];
__device__ float    g_t2  [MAXN * 128];
__device__ float    g_xf  [MAXN * 64];      // final x features [M,64]
__device__ float    g_yf  [D_NODES * 64];   // final y features [D,64]
__device__ float    g_yT  [64 * D_NODES];   // y^T [64,D]

// ---------------- helpers ----------------
__device__ __forceinline__ unsigned f2o(float f) {
    unsigned u = __float_as_uint(f);
    return (u & 0x80000000u) ? ~u : (u | 0x80000000u);
}
__device__ __forceinline__ float o2f(unsigned u) {
    u = (u & 0x80000000u) ? (u & 0x7fffffffu) : ~u;
    return __uint_as_float(u);
}

// ---------------- generic fp32 GEMM: C = act(A[N,K] @ B[K,Cn] + bias) ------
// 64x64 tile, 16x16 threads, 4x4 micro-tile, K multiple of 16, Cn mult of 64.
#define TS 64
#define KT 16
__global__ void gemm_kernel(const float* __restrict__ A, const float* __restrict__ B,
                            const float* __restrict__ bias, float* __restrict__ C,
                            int N, int K, int Cn, int relu_act)
{
    __shared__ float As[KT][TS];
    __shared__ float Bs[KT][TS];
    const int tx = threadIdx.x, ty = threadIdx.y;
    const int tid = ty * 16 + tx;
    const int row0 = blockIdx.y * TS, col0 = blockIdx.x * TS;
    float acc[4][4] = {};

    for (int k0 = 0; k0 < K; k0 += KT) {
        #pragma unroll
        for (int i = tid; i < TS * KT; i += 256) {
            int m = i / KT, kk = i % KT;
            int gm = row0 + m;
            As[kk][m] = (gm < N) ? A[(size_t)gm * K + (k0 + kk)] : 0.f;
        }
        #pragma unroll
        for (int i = tid; i < TS * KT; i += 256) {
            int kk = i / TS, n = i % TS;
            Bs[kk][n] = B[(size_t)(k0 + kk) * Cn + (col0 + n)];
        }
        __syncthreads();
        #pragma unroll
        for (int kk = 0; kk < KT; kk++) {
            float4 a4 = *(const float4*)&As[kk][ty * 4];
            float4 b4 = *(const float4*)&Bs[kk][tx * 4];
            float a[4] = {a4.x, a4.y, a4.z, a4.w};
            float b[4] = {b4.x, b4.y, b4.z, b4.w};
            #pragma unroll
            for (int i = 0; i < 4; i++)
                #pragma unroll
                for (int j = 0; j < 4; j++)
                    acc[i][j] += a[i] * b[j];
        }
        __syncthreads();
    }
    #pragma unroll
    for (int i = 0; i < 4; i++) {
        int gm = row0 + ty * 4 + i;
        if (gm >= N) continue;
        #pragma unroll
        for (int j = 0; j < 4; j++) {
            int gn = col0 + tx * 4 + j;
            float v = acc[i][j];
            if (bias) v += bias[gn];
            if (relu_act) v = fmaxf(v, 0.f);
            C[(size_t)gm * Cn + gn] = v;
        }
    }
}

// ---------------- GAT kernels ----------------
// alpha_src[n,h] = sum_c h[n,h,c]*a_src[h,c] ; same for dst
__global__ void alpha_kernel(const float* __restrict__ h,
                             const float* __restrict__ a_src,
                             const float* __restrict__ a_dst,
                             float* __restrict__ asrc, float* __restrict__ adst,
                             int N, int H, int C)
{
    int idx = blockIdx.x * blockDim.x + threadIdx.x;
    if (idx >= N * H) return;
    int n = idx / H, hh = idx % H;
    const float* hp = h + (size_t)n * H * C + hh * C;
    const float* as = a_src + hh * C;
    const float* ad = a_dst + hh * C;
    float s1 = 0.f, s2 = 0.f;
    for (int c = 0; c < C; c++) { float v = hp[c]; s1 += v * as[c]; s2 += v * ad[c]; }
    asrc[idx] = s1;
    adst[idx] = s2;
}

__global__ void init_attn(unsigned* __restrict__ emax, float* __restrict__ den, int NH)
{
    int i = blockIdx.x * blockDim.x + threadIdx.x;
    if (i < NH) { emax[i] = 0x007FFFFFu; /* f2o(-inf) */ den[i] = 0.f; }
}

// pass A: leaky-relu logits + segment max (ordered-uint atomicMax)
__global__ void edge_max(const int* __restrict__ src, const int* __restrict__ dst,
                         const float* __restrict__ asrc, const float* __restrict__ adst,
                         float* __restrict__ ebuf, unsigned* __restrict__ emax,
                         int E, int H)
{
    int idx = blockIdx.x * blockDim.x + threadIdx.x;
    if (idx >= E * H) return;
    int e = idx / H, hh = idx % H;
    int s = src[e], d = dst[e];
    float v = asrc[s * H + hh] + adst[d * H + hh];
    v = (v >= 0.f) ? v : 0.2f * v;
    ebuf[idx] = v;
    atomicMax(&emax[d * H + hh], f2o(v));
}

// pass B: exp(e - max) + segment sum
__global__ void edge_exp(const int* __restrict__ dst,
                         float* __restrict__ ebuf, const unsigned* __restrict__ emax,
                         float* __restrict__ den, int E, int H)
{
    int idx = blockIdx.x * blockDim.x + threadIdx.x;
    if (idx >= E * H) return;
    int e = idx / H, hh = idx % H;
    int d = dst[e];
    float v = expf(ebuf[idx] - o2f(emax[d * H + hh]));
    ebuf[idx] = v;
    atomicAdd(&den[d * H + hh], v);
}

// pass C: out[dst] += alpha * h[src] ; one warp per (edge, head)
__global__ void edge_scatter(const int* __restrict__ src, const int* __restrict__ dst,
                             const float* __restrict__ h, const float* __restrict__ ebuf,
                             const float* __restrict__ den, float* __restrict__ out,
                             int E, int H, int C)
{
    int gw = (blockIdx.x * blockDim.x + threadIdx.x) >> 5;
    int lane = threadIdx.x & 31;
    if (gw >= E * H) return;
    int e = gw / H, hh = gw % H;
    int s = src[e], d = dst[e];
    float coef = ebuf[gw] / (den[d * H + hh] + 1e-16f);
    const float* hp = h + (size_t)s * H * C + hh * C;
    float* op = out + (size_t)d * H * C + hh * C;
    for (int c = lane; c < C; c += 32)
        atomicAdd(&op[c], hp[c] * coef);
}

__global__ void bias_relu(const float* __restrict__ in, const float* __restrict__ b,
                          float* __restrict__ out, size_t total, int HC)
{
    size_t i = (size_t)blockIdx.x * blockDim.x + threadIdx.x;
    if (i >= total) return;
    int c = (int)(i % HC);
    out[i] = fmaxf(in[i] + b[c], 0.f);
}

__global__ void transpose64(const float* __restrict__ y, float* __restrict__ yT, int Dn)
{
    int i = blockIdx.x * blockDim.x + threadIdx.x;
    if (i >= Dn * 64) return;
    int n = i / 64, k = i % 64;
    yT[k * Dn + n] = y[i];
}

// ---------------- host orchestration ----------------
static void run_gemm(const float* A, const float* B, const float* bias, float* C,
                     int N, int K, int Cn, int act)
{
    dim3 b(16, 16), g((Cn + TS - 1) / TS, (N + TS - 1) / TS);
    gemm_kernel<<<g, b>>>(A, B, bias, C, N, K, Cn, act);
}

struct Scratch {
    float *h, *feat, *agg, *asrc, *adst, *den, *ee, *X, *t1, *t2, *xf, *yf, *yT;
    unsigned* emax;
};

static void run_gat(const float* x, int N, int Fin, const int* ei, int E,
                    const float* W, const float* a_s, const float* a_d, const float* b,
                    int H, int C, float* out, const Scratch& S)
{
    const int* src = ei;
    const int* dst = ei + E;
    run_gemm(x, W, nullptr, S.h, N, Fin, H * C, 0);
    int NH = N * H;
    alpha_kernel<<<(NH + 255) / 256, 256>>>(S.h, a_s, a_d, S.asrc, S.adst, N, H, C);
    init_attn<<<(NH + 255) / 256, 256>>>(S.emax, S.den, NH);
    cudaMemsetAsync(S.agg, 0, (size_t)N * H * C * sizeof(float));
    int EH = E * H;
    edge_max<<<(EH + 255) / 256, 256>>>(src, dst, S.asrc, S.adst, S.ee, S.emax, E, H);
    edge_exp<<<(EH + 255) / 256, 256>>>(dst, S.ee, S.emax, S.den, E, H);
    long threads = (long)EH * 32;
    edge_scatter<<<(unsigned)((threads + 255) / 256), 256>>>(src, dst, S.h, S.ee, S.den, S.agg, E, H, C);
    size_t tot = (size_t)N * H * C;
    bias_relu<<<(unsigned)((tot + 255) / 256), 256>>>(S.agg, b, out, tot, H * C);
}

extern "C" void kernel_launch(void* const* d_in, const int* in_sizes, int n_in,
                              void* d_out, int out_size)
{
    const float* x_m  = (const float*)d_in[0];
    const float* x_d  = (const float*)d_in[1];
    const int*   mm   = (const int*)d_in[2];
    const int*   dd   = (const int*)d_in[3];
    const float* W_gx1 = (const float*)d_in[4];
    const float* as_gx1 = (const float*)d_in[5];
    const float* ad_gx1 = (const float*)d_in[6];
    const float* b_gx1  = (const float*)d_in[7];
    const float* W_gx2 = (const float*)d_in[8];
    const float* as_gx2 = (const float*)d_in[9];
    const float* ad_gx2 = (const float*)d_in[10];
    const float* b_gx2  = (const float*)d_in[11];
    const float* W_gy1 = (const float*)d_in[12];
    const float* as_gy1 = (const float*)d_in[13];
    const float* ad_gy1 = (const float*)d_in[14];
    const float* b_gy1  = (const float*)d_in[15];
    const float* W_gy2 = (const float*)d_in[16];
    const float* as_gy2 = (const float*)d_in[17];
    const float* ad_gy2 = (const float*)d_in[18];
    const float* b_gy2  = (const float*)d_in[19];
    const float* lx1_W = (const float*)d_in[20];
    const float* lx1_b = (const float*)d_in[21];
    const float* lx2_W = (const float*)d_in[22];
    const float* lx2_b = (const float*)d_in[23];
    const float* lx3_W = (const float*)d_in[24];
    const float* lx3_b = (const float*)d_in[25];
    const float* ly1_W = (const float*)d_in[26];
    const float* ly1_b = (const float*)d_in[27];
    const float* ly2_W = (const float*)d_in[28];
    const float* ly2_b = (const float*)d_in[29];
    const float* ly3_W = (const float*)d_in[30];
    const float* ly3_b = (const float*)d_in[31];

    Scratch S;
    cudaGetSymbolAddress((void**)&S.h,    g_h);
    cudaGetSymbolAddress((void**)&S.feat, g_feat);
    cudaGetSymbolAddress((void**)&S.agg,  g_agg);
    cudaGetSymbolAddress((void**)&S.asrc, g_asrc);
    cudaGetSymbolAddress((void**)&S.adst, g_adst);
    cudaGetSymbolAddress((void**)&S.emax, g_emax);
    cudaGetSymbolAddress((void**)&S.den,  g_den);
    cudaGetSymbolAddress((void**)&S.ee,   g_ee);
    cudaGetSymbolAddress((void**)&S.X,    g_X);
    cudaGetSymbolAddress((void**)&S.t1,   g_t1);
    cudaGetSymbolAddress((void**)&S.t2,   g_t2);
    cudaGetSymbolAddress((void**)&S.xf,   g_xf);
    cudaGetSymbolAddress((void**)&S.yf,   g_yf);
    cudaGetSymbolAddress((void**)&S.yT,   g_yT);

    // ----- X branch (molecule graph) -----
    run_gat(x_m,   M_NODES, 64,  mm, E_MM, W_gx1, as_gx1, ad_gx1, b_gx1, 2, 128, S.feat, S);
    run_gat(S.feat, M_NODES, 256, mm, E_MM, W_gx2, as_gx2, ad_gx2, b_gx2, 1, 64,  S.X,    S);
    run_gemm(S.X,  lx1_W, lx1_b, S.t1, M_NODES, 64,  256, 1);
    run_gemm(S.t1, lx2_W, lx2_b, S.t2, M_NODES, 256, 128, 1);
    run_gemm(S.t2, lx3_W, lx3_b, S.xf, M_NODES, 128, 64,  1);

    // ----- Y branch (disease graph), reusing scratch -----
    run_gat(x_d,   D_NODES, 64,  dd, E_DD, W_gy1, as_gy1, ad_gy1, b_gy1, 2, 128, S.feat, S);
    run_gat(S.feat, D_NODES, 256, dd, E_DD, W_gy2, as_gy2, ad_gy2, b_gy2, 1, 64,  S.X,    S);
    run_gemm(S.X,  ly1_W, ly1_b, S.t1, D_NODES, 64,  256, 1);
    run_gemm(S.t1, ly2_W, ly2_b, S.t2, D_NODES, 256, 128, 1);
    run_gemm(S.t2, ly3_W, ly3_b, S.yf, D_NODES, 128, 64,  1);

    // ----- final: out = xf @ yf^T -----
    transpose64<<<(D_NODES * 64 + 255) / 256, 256>>>(S.yf, S.yT, D_NODES);
    run_gemm(S.xf, S.yT, nullptr, (float*)d_out, M_NODES, 64, D_NODES, 0);
}

// round 3
// speedup vs baseline: 1.8127x; 1.8127x over previous
#include <cuda_runtime.h>
#include <math.h>
#include <stdint.h>

// ---------------- problem constants ----------------
#define M_NODES 20000
#define D_NODES 8000
#define E_MM    320000
#define E_DD    128000
#define MAXN    20000
#define MAXHC   256
#define MAXH    2
#define MAXE    320000

#define MPAD 20096   // 157 * 128
#define DPAD 8064    // 63  * 128

// ---------------- scratch (device globals; allocation-free) ----------------
__device__ float    g_h   [MAXN * MAXHC];
__device__ float    g_feat[MAXN * MAXHC];
__device__ float    g_agg [MAXN * MAXHC];
__device__ float    g_asrc[MAXN * MAXH];
__device__ float    g_adst[MAXN * MAXH];
__device__ unsigned g_emax[MAXN * MAXH];
__device__ float    g_den [MAXN * MAXH];
__device__ float    g_ee  [MAXE * MAXH];
__device__ float    g_X   [MAXN * 64];
__device__ float    g_t1  [MAXN * 256];
__device__ float    g_t2  [MAXN * 128];
__device__ float    g_xf  [MPAD * 64];      // final x features, padded rows zero
__device__ float    g_yf  [DPAD * 64];      // final y features, padded rows zero

// ---------------- helpers ----------------
__device__ __forceinline__ unsigned f2o(float f) {
    unsigned u = __float_as_uint(f);
    return (u & 0x80000000u) ? ~u : (u | 0x80000000u);
}
__device__ __forceinline__ float o2f(unsigned u) {
    u = (u & 0x80000000u) ? (u & 0x7fffffffu) : ~u;
    return __uint_as_float(u);
}
__device__ __forceinline__ uint32_t cvt_tf32(float f) {
    uint32_t r;
    asm("cvt.rna.tf32.f32 %0, %1;" : "=r"(r) : "f"(f));
    return r;
}

// ---------------- generic fp32 GEMM: C = act(A[N,K] @ B[K,Cn] + bias) ------
#define TS 64
#define KT 16
__global__ void gemm_kernel(const float* __restrict__ A, const float* __restrict__ B,
                            const float* __restrict__ bias, float* __restrict__ C,
                            int N, int K, int Cn, int relu_act)
{
    __shared__ float As[KT][TS];
    __shared__ float Bs[KT][TS];
    const int tx = threadIdx.x, ty = threadIdx.y;
    const int tid = ty * 16 + tx;
    const int row0 = blockIdx.y * TS, col0 = blockIdx.x * TS;
    float acc[4][4] = {};

    for (int k0 = 0; k0 < K; k0 += KT) {
        #pragma unroll
        for (int i = tid; i < TS * KT; i += 256) {
            int m = i / KT, kk = i % KT;
            int gm = row0 + m;
            As[kk][m] = (gm < N) ? A[(size_t)gm * K + (k0 + kk)] : 0.f;
        }
        #pragma unroll
        for (int i = tid; i < TS * KT; i += 256) {
            int kk = i / TS, n = i % TS;
            Bs[kk][n] = B[(size_t)(k0 + kk) * Cn + (col0 + n)];
        }
        __syncthreads();
        #pragma unroll
        for (int kk = 0; kk < KT; kk++) {
            float4 a4 = *(const float4*)&As[kk][ty * 4];
            float4 b4 = *(const float4*)&Bs[kk][tx * 4];
            float a[4] = {a4.x, a4.y, a4.z, a4.w};
            float b[4] = {b4.x, b4.y, b4.z, b4.w};
            #pragma unroll
            for (int i = 0; i < 4; i++)
                #pragma unroll
                for (int j = 0; j < 4; j++)
                    acc[i][j] += a[i] * b[j];
        }
        __syncthreads();
    }
    #pragma unroll
    for (int i = 0; i < 4; i++) {
        int gm = row0 + ty * 4 + i;
        if (gm >= N) continue;
        #pragma unroll
        for (int j = 0; j < 4; j++) {
            int gn = col0 + tx * 4 + j;
            float v = acc[i][j];
            if (bias) v += bias[gn];
            if (relu_act) v = fmaxf(v, 0.f);
            C[(size_t)gm * Cn + gn] = v;
        }
    }
}

// ---------------- GAT kernels ----------------
__global__ void alpha_kernel(const float* __restrict__ h,
                             const float* __restrict__ a_src,
                             const float* __restrict__ a_dst,
                             float* __restrict__ asrc, float* __restrict__ adst,
                             int N, int H, int C)
{
    int idx = blockIdx.x * blockDim.x + threadIdx.x;
    if (idx >= N * H) return;
    int n = idx / H, hh = idx % H;
    const float* hp = h + (size_t)n * H * C + hh * C;
    const float* as = a_src + hh * C;
    const float* ad = a_dst + hh * C;
    float s1 = 0.f, s2 = 0.f;
    for (int c = 0; c < C; c++) { float v = hp[c]; s1 += v * as[c]; s2 += v * ad[c]; }
    asrc[idx] = s1;
    adst[idx] = s2;
}

__global__ void init_attn(unsigned* __restrict__ emax, float* __restrict__ den, int NH)
{
    int i = blockIdx.x * blockDim.x + threadIdx.x;
    if (i < NH) { emax[i] = 0x007FFFFFu; den[i] = 0.f; }
}

__global__ void edge_max(const int* __restrict__ src, const int* __restrict__ dst,
                         const float* __restrict__ asrc, const float* __restrict__ adst,
                         float* __restrict__ ebuf, unsigned* __restrict__ emax,
                         int E, int H)
{
    int idx = blockIdx.x * blockDim.x + threadIdx.x;
    if (idx >= E * H) return;
    int e = idx / H, hh = idx % H;
    int s = src[e], d = dst[e];
    float v = asrc[s * H + hh] + adst[d * H + hh];
    v = (v >= 0.f) ? v : 0.2f * v;
    ebuf[idx] = v;
    atomicMax(&emax[d * H + hh], f2o(v));
}

__global__ void edge_exp(const int* __restrict__ dst,
                         float* __restrict__ ebuf, const unsigned* __restrict__ emax,
                         float* __restrict__ den, int E, int H)
{
    int idx = blockIdx.x * blockDim.x + threadIdx.x;
    if (idx >= E * H) return;
    int e = idx / H, hh = idx % H;
    int d = dst[e];
    float v = expf(ebuf[idx] - o2f(emax[d * H + hh]));
    ebuf[idx] = v;
    atomicAdd(&den[d * H + hh], v);
}

__global__ void edge_scatter(const int* __restrict__ src, const int* __restrict__ dst,
                             const float* __restrict__ h, const float* __restrict__ ebuf,
                             const float* __restrict__ den, float* __restrict__ out,
                             int E, int H, int C)
{
    int gw = (blockIdx.x * blockDim.x + threadIdx.x) >> 5;
    int lane = threadIdx.x & 31;
    if (gw >= E * H) return;
    int e = gw / H, hh = gw % H;
    int s = src[e], d = dst[e];
    float coef = ebuf[gw] / (den[d * H + hh] + 1e-16f);
    const float* hp = h + (size_t)s * H * C + hh * C;
    float* op = out + (size_t)d * H * C + hh * C;
    for (int c = lane; c < C; c += 32)
        atomicAdd(&op[c], hp[c] * coef);
}

__global__ void bias_relu(const float* __restrict__ in, const float* __restrict__ b,
                          float* __restrict__ out, size_t total, int HC)
{
    size_t i = (size_t)blockIdx.x * blockDim.x + threadIdx.x;
    if (i >= total) return;
    int c = (int)(i % HC);
    out[i] = fmaxf(in[i] + b[c], 0.f);
}

// ================= final GEMM via mma.sync tf32 (base PTX, sm_80+) =========
// out[20000, 8000] = xf[20000,64] @ yf[8000,64]^T
// CTA: 128x128, 8 warps (4 m x 2 n), warp tile 32x64.
// SMEM: A[128][68], B[128][68] tf32 (padded stride 68 -> conflict-free frags).

#define FSTR 68

__device__ __forceinline__ void mma_tf32(float* d, const uint32_t* a, const uint32_t* b)
{
    asm volatile(
        "mma.sync.aligned.m16n8k8.row.col.f32.tf32.tf32.f32 "
        "{%0,%1,%2,%3}, {%4,%5,%6,%7}, {%8,%9}, {%0,%1,%2,%3};"
        : "+f"(d[0]), "+f"(d[1]), "+f"(d[2]), "+f"(d[3])
        : "r"(a[0]), "r"(a[1]), "r"(a[2]), "r"(a[3]), "r"(b[0]), "r"(b[1]));
}

__global__ void __launch_bounds__(256) final_mma_kernel(
    const float* __restrict__ A,   // [MPAD, 64] zero-padded rows
    const float* __restrict__ B,   // [DPAD, 64] zero-padded rows
    float* __restrict__ C)         // [20000, 8000]
{
    __shared__ uint32_t As[128 * FSTR];
    __shared__ uint32_t Bs[128 * FSTR];

    const int tid = threadIdx.x, wid = tid >> 5, lane = tid & 31;
    const int g = lane >> 2, t = lane & 3;         // groupID / thread-in-group
    const int wm = wid & 3, wn = wid >> 2;         // 4 x 2 warp grid
    const int m0 = blockIdx.y * 128, n0 = blockIdx.x * 128;

    // load + convert tiles: 128 rows x 64 cols each; 256 threads x 8 float4
    {
        const float* Ag = A + (size_t)m0 * 64;
        const float* Bg = B + (size_t)n0 * 64;
        #pragma unroll
        for (int i = tid; i < 2048; i += 256) {
            int row = i >> 4, c4 = (i & 15) << 2;
            float4 v = *(const float4*)(Ag + (size_t)row * 64 + c4);
            uint32_t* p = &As[row * FSTR + c4];
            p[0] = cvt_tf32(v.x); p[1] = cvt_tf32(v.y);
            p[2] = cvt_tf32(v.z); p[3] = cvt_tf32(v.w);
        }
        #pragma unroll
        for (int i = tid; i < 2048; i += 256) {
            int row = i >> 4, c4 = (i & 15) << 2;
            float4 v = *(const float4*)(Bg + (size_t)row * 64 + c4);
            uint32_t* p = &Bs[row * FSTR + c4];
            p[0] = cvt_tf32(v.x); p[1] = cvt_tf32(v.y);
            p[2] = cvt_tf32(v.z); p[3] = cvt_tf32(v.w);
        }
    }
    __syncthreads();

    float acc[2][8][4];
    #pragma unroll
    for (int i = 0; i < 2; i++)
        #pragma unroll
        for (int j = 0; j < 8; j++)
            #pragma unroll
            for (int q = 0; q < 4; q++) acc[i][j][q] = 0.f;

    const int arow = wm * 32;
    const int bcol = wn * 64;

    #pragma unroll
    for (int ks = 0; ks < 8; ks++) {
        const int k0 = ks * 8;
        uint32_t a[2][4];
        #pragma unroll
        for (int mf = 0; mf < 2; mf++) {
            int r = arow + mf * 16;
            a[mf][0] = As[(r + g)     * FSTR + k0 + t];
            a[mf][1] = As[(r + g + 8) * FSTR + k0 + t];
            a[mf][2] = As[(r + g)     * FSTR + k0 + t + 4];
            a[mf][3] = As[(r + g + 8) * FSTR + k0 + t + 4];
        }
        #pragma unroll
        for (int nf = 0; nf < 8; nf++) {
            uint32_t b[2];
            int n = bcol + nf * 8 + g;
            b[0] = Bs[n * FSTR + k0 + t];
            b[1] = Bs[n * FSTR + k0 + t + 4];
            mma_tf32(acc[0][nf], a[0], b);
            mma_tf32(acc[1][nf], a[1], b);
        }
    }

    // epilogue: thread owns (row g (+8), cols 2t, 2t+1) of each 16x8 frag
    #pragma unroll
    for (int mf = 0; mf < 2; mf++) {
        #pragma unroll
        for (int rr = 0; rr < 2; rr++) {
            int row = m0 + arow + mf * 16 + rr * 8 + g;
            if (row >= M_NODES) continue;
            float* cp = C + (size_t)row * D_NODES;
            #pragma unroll
            for (int nf = 0; nf < 8; nf++) {
                int col = n0 + bcol + nf * 8 + 2 * t;
                if (col + 1 < D_NODES) {
                    float2 v;
                    v.x = acc[mf][nf][rr * 2 + 0];
                    v.y = acc[mf][nf][rr * 2 + 1];
                    *(float2*)(cp + col) = v;
                } else if (col < D_NODES) {
                    cp[col] = acc[mf][nf][rr * 2 + 0];
                }
            }
        }
    }
}

// ---------------- host orchestration ----------------
static void run_gemm(const float* A, const float* B, const float* bias, float* C,
                     int N, int K, int Cn, int act)
{
    dim3 b(16, 16), g((Cn + TS - 1) / TS, (N + TS - 1) / TS);
    gemm_kernel<<<g, b>>>(A, B, bias, C, N, K, Cn, act);
}

struct Scratch {
    float *h, *feat, *agg, *asrc, *adst, *den, *ee, *X, *t1, *t2, *xf, *yf;
    unsigned* emax;
};

static void run_gat(const float* x, int N, int Fin, const int* ei, int E,
                    const float* W, const float* a_s, const float* a_d, const float* b,
                    int H, int C, float* out, const Scratch& S)
{
    const int* src = ei;
    const int* dst = ei + E;
    run_gemm(x, W, nullptr, S.h, N, Fin, H * C, 0);
    int NH = N * H;
    alpha_kernel<<<(NH + 255) / 256, 256>>>(S.h, a_s, a_d, S.asrc, S.adst, N, H, C);
    init_attn<<<(NH + 255) / 256, 256>>>(S.emax, S.den, NH);
    cudaMemsetAsync(S.agg, 0, (size_t)N * H * C * sizeof(float));
    int EH = E * H;
    edge_max<<<(EH + 255) / 256, 256>>>(src, dst, S.asrc, S.adst, S.ee, S.emax, E, H);
    edge_exp<<<(EH + 255) / 256, 256>>>(dst, S.ee, S.emax, S.den, E, H);
    long threads = (long)EH * 32;
    edge_scatter<<<(unsigned)((threads + 255) / 256), 256>>>(src, dst, S.h, S.ee, S.den, S.agg, E, H, C);
    size_t tot = (size_t)N * H * C;
    bias_relu<<<(unsigned)((tot + 255) / 256), 256>>>(S.agg, b, out, tot, H * C);
}

extern "C" void kernel_launch(void* const* d_in, const int* in_sizes, int n_in,
                              void* d_out, int out_size)
{
    const float* x_m  = (const float*)d_in[0];
    const float* x_d  = (const float*)d_in[1];
    const int*   mm   = (const int*)d_in[2];
    const int*   dd   = (const int*)d_in[3];
    const float* W_gx1 = (const float*)d_in[4];
    const float* as_gx1 = (const float*)d_in[5];
    const float* ad_gx1 = (const float*)d_in[6];
    const float* b_gx1  = (const float*)d_in[7];
    const float* W_gx2 = (const float*)d_in[8];
    const float* as_gx2 = (const float*)d_in[9];
    const float* ad_gx2 = (const float*)d_in[10];
    const float* b_gx2  = (const float*)d_in[11];
    const float* W_gy1 = (const float*)d_in[12];
    const float* as_gy1 = (const float*)d_in[13];
    const float* ad_gy1 = (const float*)d_in[14];
    const float* b_gy1  = (const float*)d_in[15];
    const float* W_gy2 = (const float*)d_in[16];
    const float* as_gy2 = (const float*)d_in[17];
    const float* ad_gy2 = (const float*)d_in[18];
    const float* b_gy2  = (const float*)d_in[19];
    const float* lx1_W = (const float*)d_in[20];
    const float* lx1_b = (const float*)d_in[21];
    const float* lx2_W = (const float*)d_in[22];
    const float* lx2_b = (const float*)d_in[23];
    const float* lx3_W = (const float*)d_in[24];
    const float* lx3_b = (const float*)d_in[25];
    const float* ly1_W = (const float*)d_in[26];
    const float* ly1_b = (const float*)d_in[27];
    const float* ly2_W = (const float*)d_in[28];
    const float* ly2_b = (const float*)d_in[29];
    const float* ly3_W = (const float*)d_in[30];
    const float* ly3_b = (const float*)d_in[31];

    Scratch S;
    cudaGetSymbolAddress((void**)&S.h,    g_h);
    cudaGetSymbolAddress((void**)&S.feat, g_feat);
    cudaGetSymbolAddress((void**)&S.agg,  g_agg);
    cudaGetSymbolAddress((void**)&S.asrc, g_asrc);
    cudaGetSymbolAddress((void**)&S.adst, g_adst);
    cudaGetSymbolAddress((void**)&S.emax, g_emax);
    cudaGetSymbolAddress((void**)&S.den,  g_den);
    cudaGetSymbolAddress((void**)&S.ee,   g_ee);
    cudaGetSymbolAddress((void**)&S.X,    g_X);
    cudaGetSymbolAddress((void**)&S.t1,   g_t1);
    cudaGetSymbolAddress((void**)&S.t2,   g_t2);
    cudaGetSymbolAddress((void**)&S.xf,   g_xf);
    cudaGetSymbolAddress((void**)&S.yf,   g_yf);

    // zero padded tails of xf / yf so edge tiles read zeros
    cudaMemsetAsync(S.xf + (size_t)M_NODES * 64, 0, (size_t)(MPAD - M_NODES) * 64 * sizeof(float));
    cudaMemsetAsync(S.yf + (size_t)D_NODES * 64, 0, (size_t)(DPAD - D_NODES) * 64 * sizeof(float));

    // ----- X branch -----
    run_gat(x_m,    M_NODES, 64,  mm, E_MM, W_gx1, as_gx1, ad_gx1, b_gx1, 2, 128, S.feat, S);
    run_gat(S.feat, M_NODES, 256, mm, E_MM, W_gx2, as_gx2, ad_gx2, b_gx2, 1, 64,  S.X,    S);
    run_gemm(S.X,  lx1_W, lx1_b, S.t1, M_NODES, 64,  256, 1);
    run_gemm(S.t1, lx2_W, lx2_b, S.t2, M_NODES, 256, 128, 1);
    run_gemm(S.t2, lx3_W, lx3_b, S.xf, M_NODES, 128, 64,  1);

    // ----- Y branch -----
    run_gat(x_d,    D_NODES, 64,  dd, E_DD, W_gy1, as_gy1, ad_gy1, b_gy1, 2, 128, S.feat, S);
    run_gat(S.feat, D_NODES, 256, dd, E_DD, W_gy2, as_gy2, ad_gy2, b_gy2, 1, 64,  S.X,    S);
    run_gemm(S.X,  ly1_W, ly1_b, S.t1, D_NODES, 64,  256, 1);
    run_gemm(S.t1, ly2_W, ly2_b, S.t2, D_NODES, 256, 128, 1);
    run_gemm(S.t2, ly3_W, ly3_b, S.yf, D_NODES, 128, 64,  1);

    // ----- final: out = xf @ yf^T via mma.sync tf32 -----
    dim3 grid(DPAD / 128, MPAD / 128);
    final_mma_kernel<<<grid, 256>>>(S.xf, S.yf, (float*)d_out);
}

// round 4
// speedup vs baseline: 2.7121x; 1.4962x over previous
#include <cuda_runtime.h>
#include <math.h>
#include <stdint.h>

// ---------------- problem constants ----------------
#define M_NODES 20000
#define D_NODES 8000
#define E_MM    320000
#define E_DD    128000
#define MAXN    20000
#define MAXHC   256
#define MAXH    2
#define MAXE    320000

#define MPAD 20096   // 157 * 128
#define DPAD 8064    // 63  * 128

// ---------------- scratch (device globals; allocation-free) ----------------
__device__ float    g_h   [MAXN * MAXHC];
__device__ float    g_feat[MAXN * MAXHC];
__device__ float    g_agg [MAXN * MAXHC];
__device__ float    g_asrc[MAXN * MAXH];
__device__ float    g_adst[MAXN * MAXH];
__device__ unsigned g_emax[MAXN * MAXH];
__device__ float    g_den [MAXN * MAXH];
__device__ float    g_ee  [MAXE * MAXH];
__device__ float    g_X   [MAXN * 64];
__device__ float    g_t1  [MAXN * 256];
__device__ float    g_t2  [MAXN * 128];
__device__ float    g_xf  [MPAD * 64];      // final x features, padded rows zero
__device__ float    g_yf  [DPAD * 64];      // final y features, padded rows zero

// ---------------- helpers ----------------
__device__ __forceinline__ unsigned f2o(float f) {
    unsigned u = __float_as_uint(f);
    return (u & 0x80000000u) ? ~u : (u | 0x80000000u);
}
__device__ __forceinline__ float o2f(unsigned u) {
    u = (u & 0x80000000u) ? (u & 0x7fffffffu) : ~u;
    return __uint_as_float(u);
}
__device__ __forceinline__ uint32_t cvt_tf32(float f) {
    uint32_t r;
    asm("cvt.rna.tf32.f32 %0, %1;" : "=r"(r) : "f"(f));
    return r;
}
__device__ __forceinline__ void mma_tf32(float* d, const uint32_t* a, const uint32_t* b)
{
    asm volatile(
        "mma.sync.aligned.m16n8k8.row.col.f32.tf32.tf32.f32 "
        "{%0,%1,%2,%3}, {%4,%5,%6,%7}, {%8,%9}, {%0,%1,%2,%3};"
        : "+f"(d[0]), "+f"(d[1]), "+f"(d[2]), "+f"(d[3])
        : "r"(a[0]), "r"(a[1]), "r"(a[2]), "r"(a[3]), "r"(b[0]), "r"(b[1]));
}

// ============ generic tf32 mma GEMM: C = act(A[N,K] @ B[K,Cn] + bias) ======
// CTA tile 128(m) x 64(n), K chunked by 64. Requires K % 64 == 0, Cn % 64 == 0.
// 8 warps: 4m x 2n -> warp tile 32x32.
#define GSTR 68

__global__ void __launch_bounds__(256) mma_gemm_kernel(
    const float* __restrict__ A, const float* __restrict__ B,
    const float* __restrict__ bias, float* __restrict__ C,
    int N, int K, int Cn, int relu_act)
{
    __shared__ uint32_t As[128 * GSTR];
    __shared__ uint32_t Bs[64 * GSTR];

    const int tid = threadIdx.x, wid = tid >> 5, lane = tid & 31;
    const int g = lane >> 2, t = lane & 3;
    const int wm = wid & 3, wn = wid >> 2;
    const int row0 = blockIdx.y * 128, col0 = blockIdx.x * 64;

    float acc[2][4][4];
    #pragma unroll
    for (int i = 0; i < 2; i++)
        #pragma unroll
        for (int j = 0; j < 4; j++)
            #pragma unroll
            for (int q = 0; q < 4; q++) acc[i][j][q] = 0.f;

    for (int k0 = 0; k0 < K; k0 += 64) {
        // A chunk: 128 rows x 64 k
        #pragma unroll
        for (int i = tid; i < 2048; i += 256) {
            int row = i >> 4, c4 = (i & 15) << 2;
            int gm = row0 + row;
            float4 v = make_float4(0.f, 0.f, 0.f, 0.f);
            if (gm < N) v = *(const float4*)(A + (size_t)gm * K + k0 + c4);
            uint32_t* p = &As[row * GSTR + c4];
            p[0] = cvt_tf32(v.x); p[1] = cvt_tf32(v.y);
            p[2] = cvt_tf32(v.z); p[3] = cvt_tf32(v.w);
        }
        // B chunk: 64 k-rows x 64 cols, stored transposed Bs[col][k]
        #pragma unroll
        for (int i = tid; i < 1024; i += 256) {
            int kk = i >> 4, c4 = (i & 15) << 2;
            float4 v = *(const float4*)(B + (size_t)(k0 + kk) * Cn + col0 + c4);
            Bs[(c4 + 0) * GSTR + kk] = cvt_tf32(v.x);
            Bs[(c4 + 1) * GSTR + kk] = cvt_tf32(v.y);
            Bs[(c4 + 2) * GSTR + kk] = cvt_tf32(v.z);
            Bs[(c4 + 3) * GSTR + kk] = cvt_tf32(v.w);
        }
        __syncthreads();

        #pragma unroll
        for (int ks = 0; ks < 8; ks++) {
            const int kb = ks * 8;
            uint32_t a[2][4];
            #pragma unroll
            for (int mf = 0; mf < 2; mf++) {
                int r = wm * 32 + mf * 16;
                a[mf][0] = As[(r + g)     * GSTR + kb + t];
                a[mf][1] = As[(r + g + 8) * GSTR + kb + t];
                a[mf][2] = As[(r + g)     * GSTR + kb + t + 4];
                a[mf][3] = As[(r + g + 8) * GSTR + kb + t + 4];
            }
            #pragma unroll
            for (int nf = 0; nf < 4; nf++) {
                uint32_t b[2];
                int n = wn * 32 + nf * 8 + g;
                b[0] = Bs[n * GSTR + kb + t];
                b[1] = Bs[n * GSTR + kb + t + 4];
                mma_tf32(acc[0][nf], a[0], b);
                mma_tf32(acc[1][nf], a[1], b);
            }
        }
        __syncthreads();
    }

    // epilogue
    #pragma unroll
    for (int mf = 0; mf < 2; mf++) {
        #pragma unroll
        for (int rr = 0; rr < 2; rr++) {
            int row = row0 + wm * 32 + mf * 16 + rr * 8 + g;
            if (row >= N) continue;
            float* cp = C + (size_t)row * Cn;
            #pragma unroll
            for (int nf = 0; nf < 4; nf++) {
                int col = col0 + wn * 32 + nf * 8 + 2 * t;
                float2 v;
                v.x = acc[mf][nf][rr * 2 + 0];
                v.y = acc[mf][nf][rr * 2 + 1];
                if (bias) { v.x += bias[col]; v.y += bias[col + 1]; }
                if (relu_act) { v.x = fmaxf(v.x, 0.f); v.y = fmaxf(v.y, 0.f); }
                *(float2*)(cp + col) = v;
            }
        }
    }
}

// ---------------- GAT kernels ----------------
__global__ void alpha_kernel(const float* __restrict__ h,
                             const float* __restrict__ a_src,
                             const float* __restrict__ a_dst,
                             float* __restrict__ asrc, float* __restrict__ adst,
                             int N, int H, int C)
{
    int idx = blockIdx.x * blockDim.x + threadIdx.x;
    if (idx >= N * H) return;
    int n = idx / H, hh = idx % H;
    const float* hp = h + (size_t)n * H * C + hh * C;
    const float* as = a_src + hh * C;
    const float* ad = a_dst + hh * C;
    float s1 = 0.f, s2 = 0.f;
    for (int c = 0; c < C; c++) { float v = hp[c]; s1 += v * as[c]; s2 += v * ad[c]; }
    asrc[idx] = s1;
    adst[idx] = s2;
}

__global__ void init_attn(unsigned* __restrict__ emax, float* __restrict__ den, int NH)
{
    int i = blockIdx.x * blockDim.x + threadIdx.x;
    if (i < NH) { emax[i] = 0x007FFFFFu; den[i] = 0.f; }
}

__global__ void edge_max(const int* __restrict__ src, const int* __restrict__ dst,
                         const float* __restrict__ asrc, const float* __restrict__ adst,
                         float* __restrict__ ebuf, unsigned* __restrict__ emax,
                         int E, int H)
{
    int idx = blockIdx.x * blockDim.x + threadIdx.x;
    if (idx >= E * H) return;
    int e = idx / H, hh = idx % H;
    int s = src[e], d = dst[e];
    float v = asrc[s * H + hh] + adst[d * H + hh];
    v = (v >= 0.f) ? v : 0.2f * v;
    ebuf[idx] = v;
    atomicMax(&emax[d * H + hh], f2o(v));
}

__global__ void edge_exp(const int* __restrict__ dst,
                         float* __restrict__ ebuf, const unsigned* __restrict__ emax,
                         float* __restrict__ den, int E, int H)
{
    int idx = blockIdx.x * blockDim.x + threadIdx.x;
    if (idx >= E * H) return;
    int e = idx / H, hh = idx % H;
    int d = dst[e];
    float v = expf(ebuf[idx] - o2f(emax[d * H + hh]));
    ebuf[idx] = v;
    atomicAdd(&den[d * H + hh], v);
}

// one thread per (edge, head, 4-col chunk); vector red.global.add.v4.f32
// cpe_sh = log2(C/4), h_sh = log2(H)
__global__ void edge_scatter(const int* __restrict__ src, const int* __restrict__ dst,
                             const float* __restrict__ h, const float* __restrict__ ebuf,
                             const float* __restrict__ den, float* __restrict__ out,
                             int total, int cpe_sh, int h_sh, int C)
{
    int idx = blockIdx.x * blockDim.x + threadIdx.x;
    if (idx >= total) return;
    int eh = idx >> cpe_sh;
    int c = (idx & ((1 << cpe_sh) - 1)) << 2;
    int e = eh >> h_sh;
    int hh = eh & ((1 << h_sh) - 1);
    int H = 1 << h_sh;
    int s = src[e], d = dst[e];
    float coef = ebuf[eh] / (den[d * H + hh] + 1e-16f);
    const float* hp = h + (size_t)s * H * C + hh * C + c;
    float* op = out + (size_t)d * H * C + hh * C + c;
    float4 v = *(const float4*)hp;
    v.x *= coef; v.y *= coef; v.z *= coef; v.w *= coef;
    asm volatile("red.global.add.v4.f32 [%0], {%1,%2,%3,%4};"
                 :: "l"(op), "f"(v.x), "f"(v.y), "f"(v.z), "f"(v.w) : "memory");
}

__global__ void bias_relu(const float* __restrict__ in, const float* __restrict__ b,
                          float* __restrict__ out, size_t total, int HC)
{
    size_t i = (size_t)blockIdx.x * blockDim.x + threadIdx.x;
    if (i >= total) return;
    int c = (int)(i % HC);
    out[i] = fmaxf(in[i] + b[c], 0.f);
}

// ================= final GEMM via mma.sync tf32 ============================
#define FSTR 68

__global__ void __launch_bounds__(256) final_mma_kernel(
    const float* __restrict__ A,   // [MPAD, 64] zero-padded rows
    const float* __restrict__ B,   // [DPAD, 64] zero-padded rows
    float* __restrict__ C)         // [20000, 8000]
{
    __shared__ uint32_t As[128 * FSTR];
    __shared__ uint32_t Bs[128 * FSTR];

    const int tid = threadIdx.x, wid = tid >> 5, lane = tid & 31;
    const int g = lane >> 2, t = lane & 3;
    const int wm = wid & 3, wn = wid >> 2;
    const int m0 = blockIdx.y * 128, n0 = blockIdx.x * 128;

    {
        const float* Ag = A + (size_t)m0 * 64;
        const float* Bg = B + (size_t)n0 * 64;
        #pragma unroll
        for (int i = tid; i < 2048; i += 256) {
            int row = i >> 4, c4 = (i & 15) << 2;
            float4 v = *(const float4*)(Ag + (size_t)row * 64 + c4);
            uint32_t* p = &As[row * FSTR + c4];
            p[0] = cvt_tf32(v.x); p[1] = cvt_tf32(v.y);
            p[2] = cvt_tf32(v.z); p[3] = cvt_tf32(v.w);
        }
        #pragma unroll
        for (int i = tid; i < 2048; i += 256) {
            int row = i >> 4, c4 = (i & 15) << 2;
            float4 v = *(const float4*)(Bg + (size_t)row * 64 + c4);
            uint32_t* p = &Bs[row * FSTR + c4];
            p[0] = cvt_tf32(v.x); p[1] = cvt_tf32(v.y);
            p[2] = cvt_tf32(v.z); p[3] = cvt_tf32(v.w);
        }
    }
    __syncthreads();

    float acc[2][8][4];
    #pragma unroll
    for (int i = 0; i < 2; i++)
        #pragma unroll
        for (int j = 0; j < 8; j++)
            #pragma unroll
            for (int q = 0; q < 4; q++) acc[i][j][q] = 0.f;

    const int arow = wm * 32;
    const int bcol = wn * 64;

    #pragma unroll
    for (int ks = 0; ks < 8; ks++) {
        const int k0 = ks * 8;
        uint32_t a[2][4];
        #pragma unroll
        for (int mf = 0; mf < 2; mf++) {
            int r = arow + mf * 16;
            a[mf][0] = As[(r + g)     * FSTR + k0 + t];
            a[mf][1] = As[(r + g + 8) * FSTR + k0 + t];
            a[mf][2] = As[(r + g)     * FSTR + k0 + t + 4];
            a[mf][3] = As[(r + g + 8) * FSTR + k0 + t + 4];
        }
        #pragma unroll
        for (int nf = 0; nf < 8; nf++) {
            uint32_t b[2];
            int n = bcol + nf * 8 + g;
            b[0] = Bs[n * FSTR + k0 + t];
            b[1] = Bs[n * FSTR + k0 + t + 4];
            mma_tf32(acc[0][nf], a[0], b);
            mma_tf32(acc[1][nf], a[1], b);
        }
    }

    #pragma unroll
    for (int mf = 0; mf < 2; mf++) {
        #pragma unroll
        for (int rr = 0; rr < 2; rr++) {
            int row = m0 + arow + mf * 16 + rr * 8 + g;
            if (row >= M_NODES) continue;
            float* cp = C + (size_t)row * D_NODES;
            #pragma unroll
            for (int nf = 0; nf < 8; nf++) {
                int col = n0 + bcol + nf * 8 + 2 * t;
                if (col + 1 < D_NODES) {
                    float2 v;
                    v.x = acc[mf][nf][rr * 2 + 0];
                    v.y = acc[mf][nf][rr * 2 + 1];
                    *(float2*)(cp + col) = v;
                } else if (col < D_NODES) {
                    cp[col] = acc[mf][nf][rr * 2 + 0];
                }
            }
        }
    }
}

// ---------------- host orchestration ----------------
static void run_gemm(const float* A, const float* B, const float* bias, float* C,
                     int N, int K, int Cn, int act)
{
    dim3 g(Cn / 64, (N + 127) / 128);
    mma_gemm_kernel<<<g, 256>>>(A, B, bias, C, N, K, Cn, act);
}

struct Scratch {
    float *h, *feat, *agg, *asrc, *adst, *den, *ee, *X, *t1, *t2, *xf, *yf;
    unsigned* emax;
};

static int ilog2(int v) { int s = 0; while ((1 << s) < v) s++; return s; }

static void run_gat(const float* x, int N, int Fin, const int* ei, int E,
                    const float* W, const float* a_s, const float* a_d, const float* b,
                    int H, int C, float* out, const Scratch& S)
{
    const int* src = ei;
    const int* dst = ei + E;
    run_gemm(x, W, nullptr, S.h, N, Fin, H * C, 0);
    int NH = N * H;
    alpha_kernel<<<(NH + 255) / 256, 256>>>(S.h, a_s, a_d, S.asrc, S.adst, N, H, C);
    init_attn<<<(NH + 255) / 256, 256>>>(S.emax, S.den, NH);
    cudaMemsetAsync(S.agg, 0, (size_t)N * H * C * sizeof(float));
    int EH = E * H;
    edge_max<<<(EH + 255) / 256, 256>>>(src, dst, S.asrc, S.adst, S.ee, S.emax, E, H);
    edge_exp<<<(EH + 255) / 256, 256>>>(dst, S.ee, S.emax, S.den, E, H);
    int cpe_sh = ilog2(C / 4), h_sh = ilog2(H);
    int total = EH * (C / 4);
    edge_scatter<<<(total + 255) / 256, 256>>>(src, dst, S.h, S.ee, S.den, S.agg,
                                               total, cpe_sh, h_sh, C);
    size_t tot = (size_t)N * H * C;
    bias_relu<<<(unsigned)((tot + 255) / 256), 256>>>(S.agg, b, out, tot, H * C);
}

extern "C" void kernel_launch(void* const* d_in, const int* in_sizes, int n_in,
                              void* d_out, int out_size)
{
    const float* x_m  = (const float*)d_in[0];
    const float* x_d  = (const float*)d_in[1];
    const int*   mm   = (const int*)d_in[2];
    const int*   dd   = (const int*)d_in[3];
    const float* W_gx1 = (const float*)d_in[4];
    const float* as_gx1 = (const float*)d_in[5];
    const float* ad_gx1 = (const float*)d_in[6];
    const float* b_gx1  = (const float*)d_in[7];
    const float* W_gx2 = (const float*)d_in[8];
    const float* as_gx2 = (const float*)d_in[9];
    const float* ad_gx2 = (const float*)d_in[10];
    const float* b_gx2  = (const float*)d_in[11];
    const float* W_gy1 = (const float*)d_in[12];
    const float* as_gy1 = (const float*)d_in[13];
    const float* ad_gy1 = (const float*)d_in[14];
    const float* b_gy1  = (const float*)d_in[15];
    const float* W_gy2 = (const float*)d_in[16];
    const float* as_gy2 = (const float*)d_in[17];
    const float* ad_gy2 = (const float*)d_in[18];
    const float* b_gy2  = (const float*)d_in[19];
    const float* lx1_W = (const float*)d_in[20];
    const float* lx1_b = (const float*)d_in[21];
    const float* lx2_W = (const float*)d_in[22];
    const float* lx2_b = (const float*)d_in[23];
    const float* lx3_W = (const float*)d_in[24];
    const float* lx3_b = (const float*)d_in[25];
    const float* ly1_W = (const float*)d_in[26];
    const float* ly1_b = (const float*)d_in[27];
    const float* ly2_W = (const float*)d_in[28];
    const float* ly2_b = (const float*)d_in[29];
    const float* ly3_W = (const float*)d_in[30];
    const float* ly3_b = (const float*)d_in[31];

    Scratch S;
    cudaGetSymbolAddress((void**)&S.h,    g_h);
    cudaGetSymbolAddress((void**)&S.feat, g_feat);
    cudaGetSymbolAddress((void**)&S.agg,  g_agg);
    cudaGetSymbolAddress((void**)&S.asrc, g_asrc);
    cudaGetSymbolAddress((void**)&S.adst, g_adst);
    cudaGetSymbolAddress((void**)&S.emax, g_emax);
    cudaGetSymbolAddress((void**)&S.den,  g_den);
    cudaGetSymbolAddress((void**)&S.ee,   g_ee);
    cudaGetSymbolAddress((void**)&S.X,    g_X);
    cudaGetSymbolAddress((void**)&S.t1,   g_t1);
    cudaGetSymbolAddress((void**)&S.t2,   g_t2);
    cudaGetSymbolAddress((void**)&S.xf,   g_xf);
    cudaGetSymbolAddress((void**)&S.yf,   g_yf);

    // zero padded tails of xf / yf so edge tiles read zeros
    cudaMemsetAsync(S.xf + (size_t)M_NODES * 64, 0, (size_t)(MPAD - M_NODES) * 64 * sizeof(float));
    cudaMemsetAsync(S.yf + (size_t)D_NODES * 64, 0, (size_t)(DPAD - D_NODES) * 64 * sizeof(float));

    // ----- X branch -----
    run_gat(x_m,    M_NODES, 64,  mm, E_MM, W_gx1, as_gx1, ad_gx1, b_gx1, 2, 128, S.feat, S);
    run_gat(S.feat, M_NODES, 256, mm, E_MM, W_gx2, as_gx2, ad_gx2, b_gx2, 1, 64,  S.X,    S);
    run_gemm(S.X,  lx1_W, lx1_b, S.t1, M_NODES, 64,  256, 1);
    run_gemm(S.t1, lx2_W, lx2_b, S.t2, M_NODES, 256, 128, 1);
    run_gemm(S.t2, lx3_W, lx3_b, S.xf, M_NODES, 128, 64,  1);

    // ----- Y branch -----
    run_gat(x_d,    D_NODES, 64,  dd, E_DD, W_gy1, as_gy1, ad_gy1, b_gy1, 2, 128, S.feat, S);
    run_gat(S.feat, D_NODES, 256, dd, E_DD, W_gy2, as_gy2, ad_gy2, b_gy2, 1, 64,  S.X,    S);
    run_gemm(S.X,  ly1_W, ly1_b, S.t1, D_NODES, 64,  256, 1);
    run_gemm(S.t1, ly2_W, ly2_b, S.t2, D_NODES, 256, 128, 1);
    run_gemm(S.t2, ly3_W, ly3_b, S.yf, D_NODES, 128, 64,  1);

    // ----- final: out = xf @ yf^T via mma.sync tf32 -----
    dim3 grid(DPAD / 128, MPAD / 128);
    final_mma_kernel<<<grid, 256>>>(S.xf, S.yf, (float*)d_out);
}

// round 5
// speedup vs baseline: 3.1971x; 1.1788x over previous
#include <cuda_runtime.h>
#include <math.h>
#include <stdint.h>

// ---------------- problem constants ----------------
#define M_NODES 20000
#define D_NODES 8000
#define E_MM    320000
#define E_DD    128000
#define MAXN    20000
#define MAXHC   256

#define MPAD 20096   // 157 * 128
#define DPAD 8064    // 63  * 128

// ---------------- scratch (device globals; allocation-free) ----------------
__device__ float    g_h   [MAXN * MAXHC];
__device__ float    g_feat[MAXN * MAXHC];
__device__ float    g_asrc[MAXN * 2];
__device__ float    g_adst[MAXN * 2];
__device__ float    g_X   [MAXN * 64];
__device__ float    g_t1  [MAXN * 256];
__device__ float    g_t2  [MAXN * 128];
__device__ float    g_xf  [MPAD * 64];
__device__ float    g_yf  [DPAD * 64];
// CSR scratch (per-graph, built once, reused across both layers)
__device__ int      g_rpA [M_NODES + 1];
__device__ int      g_colA[E_MM];
__device__ int      g_rpB [D_NODES + 1];
__device__ int      g_colB[E_DD];
__device__ int      g_cur [M_NODES];
__device__ int      g_deg [M_NODES];

// ---------------- helpers ----------------
__device__ __forceinline__ uint32_t cvt_tf32(float f) {
    uint32_t r;
    asm("cvt.rna.tf32.f32 %0, %1;" : "=r"(r) : "f"(f));
    return r;
}
__device__ __forceinline__ void mma_tf32(float* d, const uint32_t* a, const uint32_t* b)
{
    asm volatile(
        "mma.sync.aligned.m16n8k8.row.col.f32.tf32.tf32.f32 "
        "{%0,%1,%2,%3}, {%4,%5,%6,%7}, {%8,%9}, {%0,%1,%2,%3};"
        : "+f"(d[0]), "+f"(d[1]), "+f"(d[2]), "+f"(d[3])
        : "r"(a[0]), "r"(a[1]), "r"(a[2]), "r"(a[3]), "r"(b[0]), "r"(b[1]));
}

// ============ generic tf32 mma GEMM: C = act(A[N,K] @ B[K,Cn] + bias) ======
#define GSTR 68
__global__ void __launch_bounds__(256) mma_gemm_kernel(
    const float* __restrict__ A, const float* __restrict__ B,
    const float* __restrict__ bias, float* __restrict__ C,
    int N, int K, int Cn, int relu_act)
{
    __shared__ uint32_t As[128 * GSTR];
    __shared__ uint32_t Bs[64 * GSTR];

    const int tid = threadIdx.x, wid = tid >> 5, lane = tid & 31;
    const int g = lane >> 2, t = lane & 3;
    const int wm = wid & 3, wn = wid >> 2;
    const int row0 = blockIdx.y * 128, col0 = blockIdx.x * 64;

    float acc[2][4][4];
    #pragma unroll
    for (int i = 0; i < 2; i++)
        #pragma unroll
        for (int j = 0; j < 4; j++)
            #pragma unroll
            for (int q = 0; q < 4; q++) acc[i][j][q] = 0.f;

    for (int k0 = 0; k0 < K; k0 += 64) {
        #pragma unroll
        for (int i = tid; i < 2048; i += 256) {
            int row = i >> 4, c4 = (i & 15) << 2;
            int gm = row0 + row;
            float4 v = make_float4(0.f, 0.f, 0.f, 0.f);
            if (gm < N) v = *(const float4*)(A + (size_t)gm * K + k0 + c4);
            uint32_t* p = &As[row * GSTR + c4];
            p[0] = cvt_tf32(v.x); p[1] = cvt_tf32(v.y);
            p[2] = cvt_tf32(v.z); p[3] = cvt_tf32(v.w);
        }
        #pragma unroll
        for (int i = tid; i < 1024; i += 256) {
            int kk = i >> 4, c4 = (i & 15) << 2;
            float4 v = *(const float4*)(B + (size_t)(k0 + kk) * Cn + col0 + c4);
            Bs[(c4 + 0) * GSTR + kk] = cvt_tf32(v.x);
            Bs[(c4 + 1) * GSTR + kk] = cvt_tf32(v.y);
            Bs[(c4 + 2) * GSTR + kk] = cvt_tf32(v.z);
            Bs[(c4 + 3) * GSTR + kk] = cvt_tf32(v.w);
        }
        __syncthreads();

        #pragma unroll
        for (int ks = 0; ks < 8; ks++) {
            const int kb = ks * 8;
            uint32_t a[2][4];
            #pragma unroll
            for (int mf = 0; mf < 2; mf++) {
                int r = wm * 32 + mf * 16;
                a[mf][0] = As[(r + g)     * GSTR + kb + t];
                a[mf][1] = As[(r + g + 8) * GSTR + kb + t];
                a[mf][2] = As[(r + g)     * GSTR + kb + t + 4];
                a[mf][3] = As[(r + g + 8) * GSTR + kb + t + 4];
            }
            #pragma unroll
            for (int nf = 0; nf < 4; nf++) {
                uint32_t b[2];
                int n = wn * 32 + nf * 8 + g;
                b[0] = Bs[n * GSTR + kb + t];
                b[1] = Bs[n * GSTR + kb + t + 4];
                mma_tf32(acc[0][nf], a[0], b);
                mma_tf32(acc[1][nf], a[1], b);
            }
        }
        __syncthreads();
    }

    #pragma unroll
    for (int mf = 0; mf < 2; mf++) {
        #pragma unroll
        for (int rr = 0; rr < 2; rr++) {
            int row = row0 + wm * 32 + mf * 16 + rr * 8 + g;
            if (row >= N) continue;
            float* cp = C + (size_t)row * Cn;
            #pragma unroll
            for (int nf = 0; nf < 4; nf++) {
                int col = col0 + wn * 32 + nf * 8 + 2 * t;
                float2 v;
                v.x = acc[mf][nf][rr * 2 + 0];
                v.y = acc[mf][nf][rr * 2 + 1];
                if (bias) { v.x += bias[col]; v.y += bias[col + 1]; }
                if (relu_act) { v.x = fmaxf(v.x, 0.f); v.y = fmaxf(v.y, 0.f); }
                *(float2*)(cp + col) = v;
            }
        }
    }
}

// ---------------- CSR build ----------------
__global__ void hist_kernel(const int* __restrict__ dst, int* __restrict__ deg, int E)
{
    int i = blockIdx.x * blockDim.x + threadIdx.x;
    if (i < E) atomicAdd(&deg[dst[i]], 1);
}

__global__ void __launch_bounds__(1024) scan_kernel(const int* __restrict__ deg,
                                                    int* __restrict__ rowptr, int N)
{
    __shared__ int sums[32];
    __shared__ int carry;
    int tid = threadIdx.x;
    if (tid == 0) carry = 0;
    __syncthreads();
    for (int base = 0; base < N; base += 1024) {
        int i = base + tid;
        int v = (i < N) ? deg[i] : 0;
        int x = v;
        #pragma unroll
        for (int o = 1; o < 32; o <<= 1) {
            int y = __shfl_up_sync(~0u, x, o);
            if ((tid & 31) >= o) x += y;
        }
        if ((tid & 31) == 31) sums[tid >> 5] = x;
        __syncthreads();
        if (tid < 32) {
            int s = sums[tid];
            #pragma unroll
            for (int o = 1; o < 32; o <<= 1) {
                int y = __shfl_up_sync(~0u, s, o);
                if (tid >= o) s += y;
            }
            sums[tid] = s;
        }
        __syncthreads();
        int incl = x + ((tid >= 32) ? sums[(tid >> 5) - 1] : 0) + carry;
        if (i < N) rowptr[i + 1] = incl;
        __syncthreads();
        if (tid == 1023) carry = incl;
        __syncthreads();
    }
    if (tid == 0) rowptr[0] = 0;
}

__global__ void scatter_kernel(const int* __restrict__ src, const int* __restrict__ dst,
                               int* __restrict__ cursor, int* __restrict__ col, int E)
{
    int i = blockIdx.x * blockDim.x + threadIdx.x;
    if (i >= E) return;
    int slot = atomicAdd(&cursor[dst[i]], 1);
    col[slot] = src[i];
}

// ---------------- GAT kernels ----------------
__global__ void alpha_kernel(const float* __restrict__ h,
                             const float* __restrict__ a_src,
                             const float* __restrict__ a_dst,
                             float* __restrict__ asrc, float* __restrict__ adst,
                             int N, int H, int C)
{
    int idx = blockIdx.x * blockDim.x + threadIdx.x;
    if (idx >= N * H) return;
    int n = idx / H, hh = idx % H;
    const float* hp = h + (size_t)n * H * C + hh * C;
    const float* as = a_src + hh * C;
    const float* ad = a_dst + hh * C;
    float s1 = 0.f, s2 = 0.f;
    for (int c = 0; c < C; c++) { float v = hp[c]; s1 += v * as[c]; s2 += v * ad[c]; }
    asrc[idx] = s1;
    adst[idx] = s2;
}

// fused softmax + gather aggregation + bias + relu.
// one warp per (node, head). C = 32*CPL.
template<int H, int CPL>
__global__ void gat_aggregate(const int* __restrict__ rowptr, const int* __restrict__ col,
                              const float* __restrict__ asrc, const float* __restrict__ adst,
                              const float* __restrict__ h, const float* __restrict__ bias,
                              float* __restrict__ out, int N)
{
    const int C = 32 * CPL;
    int warp = (blockIdx.x * blockDim.x + threadIdx.x) >> 5;
    int lane = threadIdx.x & 31;
    if (warp >= N * H) return;
    int d = warp / H, hh = warp % H;
    int beg = rowptr[d], end = rowptr[d + 1];
    float ad = adst[d * H + hh];

    // online softmax stats (single pass over edges, lane-strided)
    float m = -INFINITY, den = 0.f;
    for (int i = beg + lane; i < end; i += 32) {
        float v = asrc[col[i] * H + hh] + ad;
        v = (v >= 0.f) ? v : 0.2f * v;
        if (v > m) { den = den * expf(m - v) + 1.f; m = v; }
        else den += expf(v - m);
    }
    // warp combine
    #pragma unroll
    for (int o = 16; o; o >>= 1) {
        float m2 = __shfl_xor_sync(~0u, m, o);
        float d2 = __shfl_xor_sync(~0u, den, o);
        float nm = fmaxf(m, m2);
        float f1 = (m == nm) ? 1.f : expf(m - nm);
        float f2 = (m2 == nm) ? 1.f : expf(m2 - nm);
        den = den * f1 + d2 * f2;
        m = nm;
    }
    float inv = 1.f / (den + 1e-16f);

    float acc[CPL];
    #pragma unroll
    for (int q = 0; q < CPL; q++) acc[q] = 0.f;

    for (int base = beg; base < end; base += 32) {
        int i = base + lane;
        int s = 0; float coef = 0.f;
        if (i < end) {
            s = col[i];
            float v = asrc[s * H + hh] + ad;
            v = (v >= 0.f) ? v : 0.2f * v;
            coef = expf(v - m) * inv;
        }
        int cnt = min(32, end - base);
        for (int j = 0; j < cnt; j++) {
            int sj = __shfl_sync(~0u, s, j);
            float cj = __shfl_sync(~0u, coef, j);
            const float* hp = h + ((size_t)sj * H + hh) * C + lane * CPL;
            if (CPL == 4) {
                float4 v4 = *(const float4*)hp;
                acc[0] += cj * v4.x; acc[1] += cj * v4.y;
                acc[2] += cj * v4.z; acc[3] += cj * v4.w;
            } else {
                float2 v2 = *(const float2*)hp;
                acc[0] += cj * v2.x; acc[1] += cj * v2.y;
            }
        }
    }

    float* op = out + ((size_t)d * H + hh) * C + lane * CPL;
    const float* bp = bias + hh * C + lane * CPL;
    if (CPL == 4) {
        float4 v;
        v.x = fmaxf(acc[0] + bp[0], 0.f); v.y = fmaxf(acc[1] + bp[1], 0.f);
        v.z = fmaxf(acc[2] + bp[2], 0.f); v.w = fmaxf(acc[3] + bp[3], 0.f);
        *(float4*)op = v;
    } else {
        float2 v;
        v.x = fmaxf(acc[0] + bp[0], 0.f); v.y = fmaxf(acc[1] + bp[1], 0.f);
        *(float2*)op = v;
    }
}

// ================= final GEMM via mma.sync tf32 ============================
#define FSTR 68
__global__ void __launch_bounds__(256) final_mma_kernel(
    const float* __restrict__ A, const float* __restrict__ B, float* __restrict__ C)
{
    __shared__ uint32_t As[128 * FSTR];
    __shared__ uint32_t Bs[128 * FSTR];

    const int tid = threadIdx.x, wid = tid >> 5, lane = tid & 31;
    const int g = lane >> 2, t = lane & 3;
    const int wm = wid & 3, wn = wid >> 2;
    const int m0 = blockIdx.y * 128, n0 = blockIdx.x * 128;

    {
        const float* Ag = A + (size_t)m0 * 64;
        const float* Bg = B + (size_t)n0 * 64;
        #pragma unroll
        for (int i = tid; i < 2048; i += 256) {
            int row = i >> 4, c4 = (i & 15) << 2;
            float4 v = *(const float4*)(Ag + (size_t)row * 64 + c4);
            uint32_t* p = &As[row * FSTR + c4];
            p[0] = cvt_tf32(v.x); p[1] = cvt_tf32(v.y);
            p[2] = cvt_tf32(v.z); p[3] = cvt_tf32(v.w);
        }
        #pragma unroll
        for (int i = tid; i < 2048; i += 256) {
            int row = i >> 4, c4 = (i & 15) << 2;
            float4 v = *(const float4*)(Bg + (size_t)row * 64 + c4);
            uint32_t* p = &Bs[row * FSTR + c4];
            p[0] = cvt_tf32(v.x); p[1] = cvt_tf32(v.y);
            p[2] = cvt_tf32(v.z); p[3] = cvt_tf32(v.w);
        }
    }
    __syncthreads();

    float acc[2][8][4];
    #pragma unroll
    for (int i = 0; i < 2; i++)
        #pragma unroll
        for (int j = 0; j < 8; j++)
            #pragma unroll
            for (int q = 0; q < 4; q++) acc[i][j][q] = 0.f;

    const int arow = wm * 32;
    const int bcol = wn * 64;

    #pragma unroll
    for (int ks = 0; ks < 8; ks++) {
        const int k0 = ks * 8;
        uint32_t a[2][4];
        #pragma unroll
        for (int mf = 0; mf < 2; mf++) {
            int r = arow + mf * 16;
            a[mf][0] = As[(r + g)     * FSTR + k0 + t];
            a[mf][1] = As[(r + g + 8) * FSTR + k0 + t];
            a[mf][2] = As[(r + g)     * FSTR + k0 + t + 4];
            a[mf][3] = As[(r + g + 8) * FSTR + k0 + t + 4];
        }
        #pragma unroll
        for (int nf = 0; nf < 8; nf++) {
            uint32_t b[2];
            int n = bcol + nf * 8 + g;
            b[0] = Bs[n * FSTR + k0 + t];
            b[1] = Bs[n * FSTR + k0 + t + 4];
            mma_tf32(acc[0][nf], a[0], b);
            mma_tf32(acc[1][nf], a[1], b);
        }
    }

    #pragma unroll
    for (int mf = 0; mf < 2; mf++) {
        #pragma unroll
        for (int rr = 0; rr < 2; rr++) {
            int row = m0 + arow + mf * 16 + rr * 8 + g;
            if (row >= M_NODES) continue;
            float* cp = C + (size_t)row * D_NODES;
            #pragma unroll
            for (int nf = 0; nf < 8; nf++) {
                int col = n0 + bcol + nf * 8 + 2 * t;
                if (col + 1 < D_NODES) {
                    float2 v;
                    v.x = acc[mf][nf][rr * 2 + 0];
                    v.y = acc[mf][nf][rr * 2 + 1];
                    *(float2*)(cp + col) = v;
                } else if (col < D_NODES) {
                    cp[col] = acc[mf][nf][rr * 2 + 0];
                }
            }
        }
    }
}

// ---------------- host orchestration ----------------
static void run_gemm(const float* A, const float* B, const float* bias, float* C,
                     int N, int K, int Cn, int act)
{
    dim3 g(Cn / 64, (N + 127) / 128);
    mma_gemm_kernel<<<g, 256>>>(A, B, bias, C, N, K, Cn, act);
}

struct Scratch {
    float *h, *feat, *asrc, *adst, *X, *t1, *t2, *xf, *yf;
    int *rpA, *colA, *rpB, *colB, *cur, *deg;
};

static void build_csr(const int* ei, int E, int N, int* rowptr, int* col,
                      int* cursor, int* deg)
{
    const int* src = ei;
    const int* dst = ei + E;
    cudaMemsetAsync(deg, 0, N * sizeof(int));
    hist_kernel<<<(E + 255) / 256, 256>>>(dst, deg, E);
    scan_kernel<<<1, 1024>>>(deg, rowptr, N);
    cudaMemcpyAsync(cursor, rowptr, N * sizeof(int), cudaMemcpyDeviceToDevice);
    scatter_kernel<<<(E + 255) / 256, 256>>>(src, dst, cursor, col, E);
}

template<int H, int CPL>
static void run_gat(const float* x, int N, int Fin,
                    const int* rowptr, const int* col,
                    const float* W, const float* a_s, const float* a_d, const float* b,
                    float* out, const Scratch& S)
{
    const int C = 32 * CPL;
    run_gemm(x, W, nullptr, S.h, N, Fin, H * C, 0);
    int NH = N * H;
    alpha_kernel<<<(NH + 255) / 256, 256>>>(S.h, a_s, a_d, S.asrc, S.adst, N, H, C);
    gat_aggregate<H, CPL><<<(NH + 7) / 8, 256>>>(rowptr, col, S.asrc, S.adst, S.h, b, out, N);
}

extern "C" void kernel_launch(void* const* d_in, const int* in_sizes, int n_in,
                              void* d_out, int out_size)
{
    const float* x_m  = (const float*)d_in[0];
    const float* x_d  = (const float*)d_in[1];
    const int*   mm   = (const int*)d_in[2];
    const int*   dd   = (const int*)d_in[3];
    const float* W_gx1 = (const float*)d_in[4];
    const float* as_gx1 = (const float*)d_in[5];
    const float* ad_gx1 = (const float*)d_in[6];
    const float* b_gx1  = (const float*)d_in[7];
    const float* W_gx2 = (const float*)d_in[8];
    const float* as_gx2 = (const float*)d_in[9];
    const float* ad_gx2 = (const float*)d_in[10];
    const float* b_gx2  = (const float*)d_in[11];
    const float* W_gy1 = (const float*)d_in[12];
    const float* as_gy1 = (const float*)d_in[13];
    const float* ad_gy1 = (const float*)d_in[14];
    const float* b_gy1  = (const float*)d_in[15];
    const float* W_gy2 = (const float*)d_in[16];
    const float* as_gy2 = (const float*)d_in[17];
    const float* ad_gy2 = (const float*)d_in[18];
    const float* b_gy2  = (const float*)d_in[19];
    const float* lx1_W = (const float*)d_in[20];
    const float* lx1_b = (const float*)d_in[21];
    const float* lx2_W = (const float*)d_in[22];
    const float* lx2_b = (const float*)d_in[23];
    const float* lx3_W = (const float*)d_in[24];
    const float* lx3_b = (const float*)d_in[25];
    const float* ly1_W = (const float*)d_in[26];
    const float* ly1_b = (const float*)d_in[27];
    const float* ly2_W = (const float*)d_in[28];
    const float* ly2_b = (const float*)d_in[29];
    const float* ly3_W = (const float*)d_in[30];
    const float* ly3_b = (const float*)d_in[31];

    Scratch S;
    cudaGetSymbolAddress((void**)&S.h,    g_h);
    cudaGetSymbolAddress((void**)&S.feat, g_feat);
    cudaGetSymbolAddress((void**)&S.asrc, g_asrc);
    cudaGetSymbolAddress((void**)&S.adst, g_adst);
    cudaGetSymbolAddress((void**)&S.X,    g_X);
    cudaGetSymbolAddress((void**)&S.t1,   g_t1);
    cudaGetSymbolAddress((void**)&S.t2,   g_t2);
    cudaGetSymbolAddress((void**)&S.xf,   g_xf);
    cudaGetSymbolAddress((void**)&S.yf,   g_yf);
    cudaGetSymbolAddress((void**)&S.rpA,  g_rpA);
    cudaGetSymbolAddress((void**)&S.colA, g_colA);
    cudaGetSymbolAddress((void**)&S.rpB,  g_rpB);
    cudaGetSymbolAddress((void**)&S.colB, g_colB);
    cudaGetSymbolAddress((void**)&S.cur,  g_cur);
    cudaGetSymbolAddress((void**)&S.deg,  g_deg);

    // zero padded tails of xf / yf so edge tiles read zeros
    cudaMemsetAsync(S.xf + (size_t)M_NODES * 64, 0, (size_t)(MPAD - M_NODES) * 64 * sizeof(float));
    cudaMemsetAsync(S.yf + (size_t)D_NODES * 64, 0, (size_t)(DPAD - D_NODES) * 64 * sizeof(float));

    // CSR builds (once per graph, reused by both layers)
    build_csr(mm, E_MM, M_NODES, S.rpA, S.colA, S.cur, S.deg);
    build_csr(dd, E_DD, D_NODES, S.rpB, S.colB, S.cur, S.deg);

    // ----- X branch -----
    run_gat<2, 4>(x_m,    M_NODES, 64,  S.rpA, S.colA, W_gx1, as_gx1, ad_gx1, b_gx1, S.feat, S);
    run_gat<1, 2>(S.feat, M_NODES, 256, S.rpA, S.colA, W_gx2, as_gx2, ad_gx2, b_gx2, S.X,    S);
    run_gemm(S.X,  lx1_W, lx1_b, S.t1, M_NODES, 64,  256, 1);
    run_gemm(S.t1, lx2_W, lx2_b, S.t2, M_NODES, 256, 128, 1);
    run_gemm(S.t2, lx3_W, lx3_b, S.xf, M_NODES, 128, 64,  1);

    // ----- Y branch -----
    run_gat<2, 4>(x_d,    D_NODES, 64,  S.rpB, S.colB, W_gy1, as_gy1, ad_gy1, b_gy1, S.feat, S);
    run_gat<1, 2>(S.feat, D_NODES, 256, S.rpB, S.colB, W_gy2, as_gy2, ad_gy2, b_gy2, S.X,    S);
    run_gemm(S.X,  ly1_W, ly1_b, S.t1, D_NODES, 64,  256, 1);
    run_gemm(S.t1, ly2_W, ly2_b, S.t2, D_NODES, 256, 128, 1);
    run_gemm(S.t2, ly3_W, ly3_b, S.yf, D_NODES, 128, 64,  1);

    // ----- final: out = xf @ yf^T -----
    dim3 grid(DPAD / 128, MPAD / 128);
    final_mma_kernel<<<grid, 256>>>(S.xf, S.yf, (float*)d_out);
}

// round 6
// speedup vs baseline: 3.7943x; 1.1868x over previous
#include <cuda_runtime.h>
#include <math.h>
#include <stdint.h>

// ---------------- problem constants ----------------
#define M_NODES 20000
#define D_NODES 8000
#define E_MM    320000
#define E_DD    128000

#define MPAD 20096   // 157 * 128
#define DPAD 8064    // 63  * 128

// ---------------- scratch (device globals; allocation-free) ----------------
// X-branch scratch
__device__ float    g_h   [M_NODES * 256];
__device__ float    g_feat[M_NODES * 256];
__device__ float    g_asrc[M_NODES * 2];
__device__ float    g_adst[M_NODES * 2];
__device__ float    g_X   [M_NODES * 64];
__device__ float    g_t1  [M_NODES * 256];
__device__ float    g_t2  [M_NODES * 128];
__device__ float    g_xf  [MPAD * 64];
__device__ int      g_rpA [M_NODES + 1];
__device__ int      g_colA[E_MM];
__device__ int      g_curA[M_NODES];
__device__ int      g_degA[M_NODES];
// Y-branch scratch (disjoint so branches can run concurrently)
__device__ float    g_hY   [D_NODES * 256];
__device__ float    g_featY[D_NODES * 256];
__device__ float    g_asrcY[D_NODES * 2];
__device__ float    g_adstY[D_NODES * 2];
__device__ float    g_XY   [D_NODES * 64];
__device__ float    g_t1Y  [D_NODES * 256];
__device__ float    g_t2Y  [D_NODES * 128];
__device__ float    g_yf   [DPAD * 64];
__device__ int      g_rpB  [D_NODES + 1];
__device__ int      g_colB [E_DD];
__device__ int      g_curB [D_NODES];
__device__ int      g_degB [D_NODES];

// ---------------- helpers ----------------
__device__ __forceinline__ uint32_t cvt_tf32(float f) {
    uint32_t r;
    asm("cvt.rna.tf32.f32 %0, %1;" : "=r"(r) : "f"(f));
    return r;
}
__device__ __forceinline__ void mma_tf32(float* d, const uint32_t* a, const uint32_t* b)
{
    asm volatile(
        "mma.sync.aligned.m16n8k8.row.col.f32.tf32.tf32.f32 "
        "{%0,%1,%2,%3}, {%4,%5,%6,%7}, {%8,%9}, {%0,%1,%2,%3};"
        : "+f"(d[0]), "+f"(d[1]), "+f"(d[2]), "+f"(d[3])
        : "r"(a[0]), "r"(a[1]), "r"(a[2]), "r"(a[3]), "r"(b[0]), "r"(b[1]));
}

// ============ generic tf32 mma GEMM: C = act(A[N,K] @ B[K,Cn] + bias) ======
#define GSTR 68
__global__ void __launch_bounds__(256) mma_gemm_kernel(
    const float* __restrict__ A, const float* __restrict__ B,
    const float* __restrict__ bias, float* __restrict__ C,
    int N, int K, int Cn, int relu_act)
{
    __shared__ uint32_t As[128 * GSTR];
    __shared__ uint32_t Bs[64 * GSTR];

    const int tid = threadIdx.x, wid = tid >> 5, lane = tid & 31;
    const int g = lane >> 2, t = lane & 3;
    const int wm = wid & 3, wn = wid >> 2;
    const int row0 = blockIdx.y * 128, col0 = blockIdx.x * 64;

    float acc[2][4][4];
    #pragma unroll
    for (int i = 0; i < 2; i++)
        #pragma unroll
        for (int j = 0; j < 4; j++)
            #pragma unroll
            for (int q = 0; q < 4; q++) acc[i][j][q] = 0.f;

    for (int k0 = 0; k0 < K; k0 += 64) {
        #pragma unroll
        for (int i = tid; i < 2048; i += 256) {
            int row = i >> 4, c4 = (i & 15) << 2;
            int gm = row0 + row;
            float4 v = make_float4(0.f, 0.f, 0.f, 0.f);
            if (gm < N) v = *(const float4*)(A + (size_t)gm * K + k0 + c4);
            uint32_t* p = &As[row * GSTR + c4];
            p[0] = cvt_tf32(v.x); p[1] = cvt_tf32(v.y);
            p[2] = cvt_tf32(v.z); p[3] = cvt_tf32(v.w);
        }
        #pragma unroll
        for (int i = tid; i < 1024; i += 256) {
            int kk = i >> 4, c4 = (i & 15) << 2;
            float4 v = *(const float4*)(B + (size_t)(k0 + kk) * Cn + col0 + c4);
            Bs[(c4 + 0) * GSTR + kk] = cvt_tf32(v.x);
            Bs[(c4 + 1) * GSTR + kk] = cvt_tf32(v.y);
            Bs[(c4 + 2) * GSTR + kk] = cvt_tf32(v.z);
            Bs[(c4 + 3) * GSTR + kk] = cvt_tf32(v.w);
        }
        __syncthreads();

        #pragma unroll
        for (int ks = 0; ks < 8; ks++) {
            const int kb = ks * 8;
            uint32_t a[2][4];
            #pragma unroll
            for (int mf = 0; mf < 2; mf++) {
                int r = wm * 32 + mf * 16;
                a[mf][0] = As[(r + g)     * GSTR + kb + t];
                a[mf][1] = As[(r + g + 8) * GSTR + kb + t];
                a[mf][2] = As[(r + g)     * GSTR + kb + t + 4];
                a[mf][3] = As[(r + g + 8) * GSTR + kb + t + 4];
            }
            #pragma unroll
            for (int nf = 0; nf < 4; nf++) {
                uint32_t b[2];
                int n = wn * 32 + nf * 8 + g;
                b[0] = Bs[n * GSTR + kb + t];
                b[1] = Bs[n * GSTR + kb + t + 4];
                mma_tf32(acc[0][nf], a[0], b);
                mma_tf32(acc[1][nf], a[1], b);
            }
        }
        __syncthreads();
    }

    #pragma unroll
    for (int mf = 0; mf < 2; mf++) {
        #pragma unroll
        for (int rr = 0; rr < 2; rr++) {
            int row = row0 + wm * 32 + mf * 16 + rr * 8 + g;
            if (row >= N) continue;
            float* cp = C + (size_t)row * Cn;
            #pragma unroll
            for (int nf = 0; nf < 4; nf++) {
                int col = col0 + wn * 32 + nf * 8 + 2 * t;
                float2 v;
                v.x = acc[mf][nf][rr * 2 + 0];
                v.y = acc[mf][nf][rr * 2 + 1];
                if (bias) { v.x += bias[col]; v.y += bias[col + 1]; }
                if (relu_act) { v.x = fmaxf(v.x, 0.f); v.y = fmaxf(v.y, 0.f); }
                *(float2*)(cp + col) = v;
            }
        }
    }
}

// ---------------- CSR build ----------------
__global__ void hist_kernel(const int* __restrict__ dst, int* __restrict__ deg, int E)
{
    int i = blockIdx.x * blockDim.x + threadIdx.x;
    if (i < E) atomicAdd(&deg[dst[i]], 1);
}

__global__ void __launch_bounds__(1024) scan_kernel(const int* __restrict__ deg,
                                                    int* __restrict__ rowptr, int N)
{
    __shared__ int sums[32];
    __shared__ int carry;
    int tid = threadIdx.x;
    if (tid == 0) carry = 0;
    __syncthreads();
    for (int base = 0; base < N; base += 1024) {
        int i = base + tid;
        int v = (i < N) ? deg[i] : 0;
        int x = v;
        #pragma unroll
        for (int o = 1; o < 32; o <<= 1) {
            int y = __shfl_up_sync(~0u, x, o);
            if ((tid & 31) >= o) x += y;
        }
        if ((tid & 31) == 31) sums[tid >> 5] = x;
        __syncthreads();
        if (tid < 32) {
            int s = sums[tid];
            #pragma unroll
            for (int o = 1; o < 32; o <<= 1) {
                int y = __shfl_up_sync(~0u, s, o);
                if (tid >= o) s += y;
            }
            sums[tid] = s;
        }
        __syncthreads();
        int incl = x + ((tid >= 32) ? sums[(tid >> 5) - 1] : 0) + carry;
        if (i < N) rowptr[i + 1] = incl;
        __syncthreads();
        if (tid == 1023) carry = incl;
        __syncthreads();
    }
    if (tid == 0) rowptr[0] = 0;
}

__global__ void scatter_kernel(const int* __restrict__ src, const int* __restrict__ dst,
                               int* __restrict__ cursor, int* __restrict__ col, int E)
{
    int i = blockIdx.x * blockDim.x + threadIdx.x;
    if (i >= E) return;
    int slot = atomicAdd(&cursor[dst[i]], 1);
    col[slot] = src[i];
}

// ---------------- GAT kernels ----------------
__global__ void alpha_kernel(const float* __restrict__ h,
                             const float* __restrict__ a_src,
                             const float* __restrict__ a_dst,
                             float* __restrict__ asrc, float* __restrict__ adst,
                             int N, int H, int C)
{
    int idx = blockIdx.x * blockDim.x + threadIdx.x;
    if (idx >= N * H) return;
    int n = idx / H, hh = idx % H;
    const float* hp = h + (size_t)n * H * C + hh * C;
    const float* as = a_src + hh * C;
    const float* ad = a_dst + hh * C;
    float s1 = 0.f, s2 = 0.f;
    for (int c = 0; c < C; c++) { float v = hp[c]; s1 += v * as[c]; s2 += v * ad[c]; }
    asrc[idx] = s1;
    adst[idx] = s2;
}

// fused softmax + gather aggregation + bias + relu. one warp per (node, head).
template<int H, int CPL>
__global__ void gat_aggregate(const int* __restrict__ rowptr, const int* __restrict__ col,
                              const float* __restrict__ asrc, const float* __restrict__ adst,
                              const float* __restrict__ h, const float* __restrict__ bias,
                              float* __restrict__ out, int N)
{
    const int C = 32 * CPL;
    int warp = (blockIdx.x * blockDim.x + threadIdx.x) >> 5;
    int lane = threadIdx.x & 31;
    if (warp >= N * H) return;
    int d = warp / H, hh = warp % H;
    int beg = rowptr[d], end = rowptr[d + 1];
    float ad = adst[d * H + hh];

    float m = -INFINITY, den = 0.f;
    for (int i = beg + lane; i < end; i += 32) {
        float v = asrc[col[i] * H + hh] + ad;
        v = (v >= 0.f) ? v : 0.2f * v;
        if (v > m) { den = den * expf(m - v) + 1.f; m = v; }
        else den += expf(v - m);
    }
    #pragma unroll
    for (int o = 16; o; o >>= 1) {
        float m2 = __shfl_xor_sync(~0u, m, o);
        float d2 = __shfl_xor_sync(~0u, den, o);
        float nm = fmaxf(m, m2);
        float f1 = (m == nm) ? 1.f : expf(m - nm);
        float f2 = (m2 == nm) ? 1.f : expf(m2 - nm);
        den = den * f1 + d2 * f2;
        m = nm;
    }
    float inv = 1.f / (den + 1e-16f);

    float acc[CPL];
    #pragma unroll
    for (int q = 0; q < CPL; q++) acc[q] = 0.f;

    for (int base = beg; base < end; base += 32) {
        int i = base + lane;
        int s = 0; float coef = 0.f;
        if (i < end) {
            s = col[i];
            float v = asrc[s * H + hh] + ad;
            v = (v >= 0.f) ? v : 0.2f * v;
            coef = expf(v - m) * inv;
        }
        int cnt = min(32, end - base);
        for (int j = 0; j < cnt; j++) {
            int sj = __shfl_sync(~0u, s, j);
            float cj = __shfl_sync(~0u, coef, j);
            const float* hp = h + ((size_t)sj * H + hh) * C + lane * CPL;
            if (CPL == 4) {
                float4 v4 = *(const float4*)hp;
                acc[0] += cj * v4.x; acc[1] += cj * v4.y;
                acc[2] += cj * v4.z; acc[3] += cj * v4.w;
            } else {
                float2 v2 = *(const float2*)hp;
                acc[0] += cj * v2.x; acc[1] += cj * v2.y;
            }
        }
    }

    float* op = out + ((size_t)d * H + hh) * C + lane * CPL;
    const float* bp = bias + hh * C + lane * CPL;
    if (CPL == 4) {
        float4 v;
        v.x = fmaxf(acc[0] + bp[0], 0.f); v.y = fmaxf(acc[1] + bp[1], 0.f);
        v.z = fmaxf(acc[2] + bp[2], 0.f); v.w = fmaxf(acc[3] + bp[3], 0.f);
        *(float4*)op = v;
    } else {
        float2 v;
        v.x = fmaxf(acc[0] + bp[0], 0.f); v.y = fmaxf(acc[1] + bp[1], 0.f);
        *(float2*)op = v;
    }
}

// ================= final GEMM via mma.sync tf32 ============================
// t-major smem layout: elem (row, col) at [row*ASTR + (col&3)*18 + (col>>2)]
// -> per k-step, fragment pairs (t, t+4) are one aligned LDS.64, conflict-free.
#define ASTR 72
__global__ void __launch_bounds__(256) final_mma_kernel(
    const float* __restrict__ A, const float* __restrict__ B, float* __restrict__ C)
{
    __shared__ uint32_t As[128 * ASTR];
    __shared__ uint32_t Bs[128 * ASTR];

    const int tid = threadIdx.x, wid = tid >> 5, lane = tid & 31;
    const int g = lane >> 2, t = lane & 3;
    const int wm = wid & 3, wn = wid >> 2;
    const int m0 = blockIdx.y * 128, n0 = blockIdx.x * 128;

    {
        const float* Ag = A + (size_t)m0 * 64;
        const float* Bg = B + (size_t)n0 * 64;
        #pragma unroll
        for (int i = tid; i < 2048; i += 256) {
            int row = i >> 4, c4 = (i & 15) << 2;
            float4 v = *(const float4*)(Ag + (size_t)row * 64 + c4);
            uint32_t* p = &As[row * ASTR + (c4 >> 2)];
            p[0]  = cvt_tf32(v.x); p[18] = cvt_tf32(v.y);
            p[36] = cvt_tf32(v.z); p[54] = cvt_tf32(v.w);
        }
        #pragma unroll
        for (int i = tid; i < 2048; i += 256) {
            int row = i >> 4, c4 = (i & 15) << 2;
            float4 v = *(const float4*)(Bg + (size_t)row * 64 + c4);
            uint32_t* p = &Bs[row * ASTR + (c4 >> 2)];
            p[0]  = cvt_tf32(v.x); p[18] = cvt_tf32(v.y);
            p[36] = cvt_tf32(v.z); p[54] = cvt_tf32(v.w);
        }
    }
    __syncthreads();

    float acc[2][8][4];
    #pragma unroll
    for (int i = 0; i < 2; i++)
        #pragma unroll
        for (int j = 0; j < 8; j++)
            #pragma unroll
            for (int q = 0; q < 4; q++) acc[i][j][q] = 0.f;

    const int arow = wm * 32;
    const int bcol = wn * 64;
    const int toff = t * 18;

    #pragma unroll
    for (int ks = 0; ks < 8; ks++) {
        const int kb2 = ks * 2;
        uint32_t a[2][4];
        #pragma unroll
        for (int mf = 0; mf < 2; mf++) {
            int r = arow + mf * 16;
            uint2 lo = *(const uint2*)&As[(r + g)     * ASTR + toff + kb2];
            uint2 hi = *(const uint2*)&As[(r + g + 8) * ASTR + toff + kb2];
            a[mf][0] = lo.x; a[mf][2] = lo.y;
            a[mf][1] = hi.x; a[mf][3] = hi.y;
        }
        #pragma unroll
        for (int nf = 0; nf < 8; nf++) {
            int n = bcol + nf * 8 + g;
            uint2 bb = *(const uint2*)&Bs[n * ASTR + toff + kb2];
            uint32_t b[2] = {bb.x, bb.y};
            mma_tf32(acc[0][nf], a[0], b);
            mma_tf32(acc[1][nf], a[1], b);
        }
    }

    #pragma unroll
    for (int mf = 0; mf < 2; mf++) {
        #pragma unroll
        for (int rr = 0; rr < 2; rr++) {
            int row = m0 + arow + mf * 16 + rr * 8 + g;
            if (row >= M_NODES) continue;
            float* cp = C + (size_t)row * D_NODES;
            #pragma unroll
            for (int nf = 0; nf < 8; nf++) {
                int col = n0 + bcol + nf * 8 + 2 * t;
                if (col + 1 < D_NODES) {
                    float2 v;
                    v.x = acc[mf][nf][rr * 2 + 0];
                    v.y = acc[mf][nf][rr * 2 + 1];
                    *(float2*)(cp + col) = v;
                } else if (col < D_NODES) {
                    cp[col] = acc[mf][nf][rr * 2 + 0];
                }
            }
        }
    }
}

// ---------------- host orchestration ----------------
static void run_gemm(const float* A, const float* B, const float* bias, float* C,
                     int N, int K, int Cn, int act, cudaStream_t st)
{
    dim3 g(Cn / 64, (N + 127) / 128);
    mma_gemm_kernel<<<g, 256, 0, st>>>(A, B, bias, C, N, K, Cn, act);
}

static void build_csr(const int* ei, int E, int N, int* rowptr, int* col,
                      int* cursor, int* deg, cudaStream_t st)
{
    const int* src = ei;
    const int* dst = ei + E;
    cudaMemsetAsync(deg, 0, N * sizeof(int), st);
    hist_kernel<<<(E + 255) / 256, 256, 0, st>>>(dst, deg, E);
    scan_kernel<<<1, 1024, 0, st>>>(deg, rowptr, N);
    cudaMemcpyAsync(cursor, rowptr, N * sizeof(int), cudaMemcpyDeviceToDevice, st);
    scatter_kernel<<<(E + 255) / 256, 256, 0, st>>>(src, dst, cursor, col, E);
}

template<int H, int CPL>
static void run_gat(const float* x, int N, int Fin,
                    const int* rowptr, const int* col,
                    const float* W, const float* a_s, const float* a_d, const float* b,
                    float* h, float* asrc, float* adst, float* out, cudaStream_t st)
{
    const int C = 32 * CPL;
    run_gemm(x, W, nullptr, h, N, Fin, H * C, 0, st);
    int NH = N * H;
    alpha_kernel<<<(NH + 255) / 256, 256, 0, st>>>(h, a_s, a_d, asrc, adst, N, H, C);
    gat_aggregate<H, CPL><<<(NH + 7) / 8, 256, 0, st>>>(rowptr, col, asrc, adst, h, b, out, N);
}

extern "C" void kernel_launch(void* const* d_in, const int* in_sizes, int n_in,
                              void* d_out, int out_size)
{
    const float* x_m  = (const float*)d_in[0];
    const float* x_d  = (const float*)d_in[1];
    const int*   mm   = (const int*)d_in[2];
    const int*   dd   = (const int*)d_in[3];
    const float* W_gx1 = (const float*)d_in[4];
    const float* as_gx1 = (const float*)d_in[5];
    const float* ad_gx1 = (const float*)d_in[6];
    const float* b_gx1  = (const float*)d_in[7];
    const float* W_gx2 = (const float*)d_in[8];
    const float* as_gx2 = (const float*)d_in[9];
    const float* ad_gx2 = (const float*)d_in[10];
    const float* b_gx2  = (const float*)d_in[11];
    const float* W_gy1 = (const float*)d_in[12];
    const float* as_gy1 = (const float*)d_in[13];
    const float* ad_gy1 = (const float*)d_in[14];
    const float* b_gy1  = (const float*)d_in[15];
    const float* W_gy2 = (const float*)d_in[16];
    const float* as_gy2 = (const float*)d_in[17];
    const float* ad_gy2 = (const float*)d_in[18];
    const float* b_gy2  = (const float*)d_in[19];
    const float* lx1_W = (const float*)d_in[20];
    const float* lx1_b = (const float*)d_in[21];
    const float* lx2_W = (const float*)d_in[22];
    const float* lx2_b = (const float*)d_in[23];
    const float* lx3_W = (const float*)d_in[24];
    const float* lx3_b = (const float*)d_in[25];
    const float* ly1_W = (const float*)d_in[26];
    const float* ly1_b = (const float*)d_in[27];
    const float* ly2_W = (const float*)d_in[28];
    const float* ly2_b = (const float*)d_in[29];
    const float* ly3_W = (const float*)d_in[30];
    const float* ly3_b = (const float*)d_in[31];

    float *h, *feat, *asrc, *adst, *X, *t1, *t2, *xf;
    float *hY, *featY, *asrcY, *adstY, *XY, *t1Y, *t2Y, *yf;
    int *rpA, *colA, *curA, *degA, *rpB, *colB, *curB, *degB;
    cudaGetSymbolAddress((void**)&h,    g_h);
    cudaGetSymbolAddress((void**)&feat, g_feat);
    cudaGetSymbolAddress((void**)&asrc, g_asrc);
    cudaGetSymbolAddress((void**)&adst, g_adst);
    cudaGetSymbolAddress((void**)&X,    g_X);
    cudaGetSymbolAddress((void**)&t1,   g_t1);
    cudaGetSymbolAddress((void**)&t2,   g_t2);
    cudaGetSymbolAddress((void**)&xf,   g_xf);
    cudaGetSymbolAddress((void**)&rpA,  g_rpA);
    cudaGetSymbolAddress((void**)&colA, g_colA);
    cudaGetSymbolAddress((void**)&curA, g_curA);
    cudaGetSymbolAddress((void**)&degA, g_degA);
    cudaGetSymbolAddress((void**)&hY,    g_hY);
    cudaGetSymbolAddress((void**)&featY, g_featY);
    cudaGetSymbolAddress((void**)&asrcY, g_asrcY);
    cudaGetSymbolAddress((void**)&adstY, g_adstY);
    cudaGetSymbolAddress((void**)&XY,    g_XY);
    cudaGetSymbolAddress((void**)&t1Y,   g_t1Y);
    cudaGetSymbolAddress((void**)&t2Y,   g_t2Y);
    cudaGetSymbolAddress((void**)&yf,    g_yf);
    cudaGetSymbolAddress((void**)&rpB,  g_rpB);
    cudaGetSymbolAddress((void**)&colB, g_colB);
    cudaGetSymbolAddress((void**)&curB, g_curB);
    cudaGetSymbolAddress((void**)&degB, g_degB);

    // fork a side stream for the Y branch (capture-safe fork/join pattern).
    cudaStream_t sY = 0;
    cudaEvent_t eFork = 0, eJoin = 0;
    bool forked = (cudaStreamCreateWithFlags(&sY, cudaStreamNonBlocking) == cudaSuccess);
    if (forked) {
        forked = (cudaEventCreateWithFlags(&eFork, cudaEventDisableTiming) == cudaSuccess)
              && (cudaEventCreateWithFlags(&eJoin, cudaEventDisableTiming) == cudaSuccess);
    }
    cudaStream_t sy = forked ? sY : 0;
    if (forked) {
        cudaEventRecord(eFork, 0);
        cudaStreamWaitEvent(sY, eFork, 0);
    }

    // ----- X branch (stream 0) -----
    cudaMemsetAsync(xf + (size_t)M_NODES * 64, 0, (size_t)(MPAD - M_NODES) * 64 * sizeof(float), 0);
    build_csr(mm, E_MM, M_NODES, rpA, colA, curA, degA, 0);
    run_gat<2, 4>(x_m,  M_NODES, 64,  rpA, colA, W_gx1, as_gx1, ad_gx1, b_gx1, h, asrc, adst, feat, 0);
    run_gat<1, 2>(feat, M_NODES, 256, rpA, colA, W_gx2, as_gx2, ad_gx2, b_gx2, h, asrc, adst, X, 0);
    run_gemm(X,  lx1_W, lx1_b, t1, M_NODES, 64,  256, 1, 0);
    run_gemm(t1, lx2_W, lx2_b, t2, M_NODES, 256, 128, 1, 0);
    run_gemm(t2, lx3_W, lx3_b, xf, M_NODES, 128, 64,  1, 0);

    // ----- Y branch (side stream) -----
    cudaMemsetAsync(yf + (size_t)D_NODES * 64, 0, (size_t)(DPAD - D_NODES) * 64 * sizeof(float), sy);
    build_csr(dd, E_DD, D_NODES, rpB, colB, curB, degB, sy);
    run_gat<2, 4>(x_d,   D_NODES, 64,  rpB, colB, W_gy1, as_gy1, ad_gy1, b_gy1, hY, asrcY, adstY, featY, sy);
    run_gat<1, 2>(featY, D_NODES, 256, rpB, colB, W_gy2, as_gy2, ad_gy2, b_gy2, hY, asrcY, adstY, XY, sy);
    run_gemm(XY,  ly1_W, ly1_b, t1Y, D_NODES, 64,  256, 1, sy);
    run_gemm(t1Y, ly2_W, ly2_b, t2Y, D_NODES, 256, 128, 1, sy);
    run_gemm(t2Y, ly3_W, ly3_b, yf,  D_NODES, 128, 64,  1, sy);

    if (forked) {
        cudaEventRecord(eJoin, sY);
        cudaStreamWaitEvent(0, eJoin, 0);
    }

    // ----- final: out = xf @ yf^T (stream 0) -----
    dim3 grid(DPAD / 128, MPAD / 128);
    final_mma_kernel<<<grid, 256, 0, 0>>>(xf, yf, (float*)d_out);
    // streams/events intentionally not destroyed: kernel_launch only runs
    // during correctness + capture (never in the timed replay), and destroying
    // a stream that participated in an active capture is invalid.
}

// round 7
// speedup vs baseline: 3.8299x; 1.0094x over previous
#include <cuda_runtime.h>
#include <math.h>
#include <stdint.h>

// ---------------- problem constants ----------------
#define M_NODES 20000
#define D_NODES 8000
#define E_MM    320000
#define E_DD    128000

#define MPAD 20096   // 157 * 128
#define DPAD 8064    // 63  * 128

// ---------------- scratch (device globals; allocation-free) ----------------
// X-branch scratch
__device__ float    g_h   [M_NODES * 256];
__device__ float    g_feat[M_NODES * 256];
__device__ float    g_asrc[M_NODES * 2];
__device__ float    g_adst[M_NODES * 2];
__device__ float    g_X   [M_NODES * 64];
__device__ float    g_t1  [M_NODES * 256];
__device__ float    g_t2  [M_NODES * 128];
__device__ float    g_xf  [MPAD * 64];
__device__ int      g_rpA [M_NODES + 1];
__device__ int      g_colA[E_MM];
__device__ int      g_curA[M_NODES];
__device__ int      g_degA[M_NODES];
// Y-branch scratch (disjoint so branches can run concurrently)
__device__ float    g_hY   [D_NODES * 256];
__device__ float    g_featY[D_NODES * 256];
__device__ float    g_asrcY[D_NODES * 2];
__device__ float    g_adstY[D_NODES * 2];
__device__ float    g_XY   [D_NODES * 64];
__device__ float    g_t1Y  [D_NODES * 256];
__device__ float    g_t2Y  [D_NODES * 128];
__device__ float    g_yf   [DPAD * 64];
__device__ int      g_rpB  [D_NODES + 1];
__device__ int      g_colB [E_DD];
__device__ int      g_curB [D_NODES];
__device__ int      g_degB [D_NODES];

// ---------------- helpers ----------------
__device__ __forceinline__ uint32_t cvt_tf32(float f) {
    uint32_t r;
    asm("cvt.rna.tf32.f32 %0, %1;" : "=r"(r) : "f"(f));
    return r;
}
__device__ __forceinline__ void mma_tf32(float* d, const uint32_t* a, const uint32_t* b)
{
    asm volatile(
        "mma.sync.aligned.m16n8k8.row.col.f32.tf32.tf32.f32 "
        "{%0,%1,%2,%3}, {%4,%5,%6,%7}, {%8,%9}, {%0,%1,%2,%3};"
        : "+f"(d[0]), "+f"(d[1]), "+f"(d[2]), "+f"(d[3])
        : "r"(a[0]), "r"(a[1]), "r"(a[2]), "r"(a[3]), "r"(b[0]), "r"(b[1]));
}

// ============ generic tf32 mma GEMM: C = act(A[N,K] @ B[K,Cn] + bias) ======
#define GSTR 68
__global__ void __launch_bounds__(256) mma_gemm_kernel(
    const float* __restrict__ A, const float* __restrict__ B,
    const float* __restrict__ bias, float* __restrict__ C,
    int N, int K, int Cn, int relu_act)
{
    __shared__ uint32_t As[128 * GSTR];
    __shared__ uint32_t Bs[64 * GSTR];

    const int tid = threadIdx.x, wid = tid >> 5, lane = tid & 31;
    const int g = lane >> 2, t = lane & 3;
    const int wm = wid & 3, wn = wid >> 2;
    const int row0 = blockIdx.y * 128, col0 = blockIdx.x * 64;

    float acc[2][4][4];
    #pragma unroll
    for (int i = 0; i < 2; i++)
        #pragma unroll
        for (int j = 0; j < 4; j++)
            #pragma unroll
            for (int q = 0; q < 4; q++) acc[i][j][q] = 0.f;

    for (int k0 = 0; k0 < K; k0 += 64) {
        #pragma unroll
        for (int i = tid; i < 2048; i += 256) {
            int row = i >> 4, c4 = (i & 15) << 2;
            int gm = row0 + row;
            float4 v = make_float4(0.f, 0.f, 0.f, 0.f);
            if (gm < N) v = *(const float4*)(A + (size_t)gm * K + k0 + c4);
            uint32_t* p = &As[row * GSTR + c4];
            p[0] = cvt_tf32(v.x); p[1] = cvt_tf32(v.y);
            p[2] = cvt_tf32(v.z); p[3] = cvt_tf32(v.w);
        }
        #pragma unroll
        for (int i = tid; i < 1024; i += 256) {
            int kk = i >> 4, c4 = (i & 15) << 2;
            float4 v = *(const float4*)(B + (size_t)(k0 + kk) * Cn + col0 + c4);
            Bs[(c4 + 0) * GSTR + kk] = cvt_tf32(v.x);
            Bs[(c4 + 1) * GSTR + kk] = cvt_tf32(v.y);
            Bs[(c4 + 2) * GSTR + kk] = cvt_tf32(v.z);
            Bs[(c4 + 3) * GSTR + kk] = cvt_tf32(v.w);
        }
        __syncthreads();

        #pragma unroll
        for (int ks = 0; ks < 8; ks++) {
            const int kb = ks * 8;
            uint32_t a[2][4];
            #pragma unroll
            for (int mf = 0; mf < 2; mf++) {
                int r = wm * 32 + mf * 16;
                a[mf][0] = As[(r + g)     * GSTR + kb + t];
                a[mf][1] = As[(r + g + 8) * GSTR + kb + t];
                a[mf][2] = As[(r + g)     * GSTR + kb + t + 4];
                a[mf][3] = As[(r + g + 8) * GSTR + kb + t + 4];
            }
            #pragma unroll
            for (int nf = 0; nf < 4; nf++) {
                uint32_t b[2];
                int n = wn * 32 + nf * 8 + g;
                b[0] = Bs[n * GSTR + kb + t];
                b[1] = Bs[n * GSTR + kb + t + 4];
                mma_tf32(acc[0][nf], a[0], b);
                mma_tf32(acc[1][nf], a[1], b);
            }
        }
        __syncthreads();
    }

    #pragma unroll
    for (int mf = 0; mf < 2; mf++) {
        #pragma unroll
        for (int rr = 0; rr < 2; rr++) {
            int row = row0 + wm * 32 + mf * 16 + rr * 8 + g;
            if (row >= N) continue;
            float* cp = C + (size_t)row * Cn;
            #pragma unroll
            for (int nf = 0; nf < 4; nf++) {
                int col = col0 + wn * 32 + nf * 8 + 2 * t;
                float2 v;
                v.x = acc[mf][nf][rr * 2 + 0];
                v.y = acc[mf][nf][rr * 2 + 1];
                if (bias) { v.x += bias[col]; v.y += bias[col + 1]; }
                if (relu_act) { v.x = fmaxf(v.x, 0.f); v.y = fmaxf(v.y, 0.f); }
                *(float2*)(cp + col) = v;
            }
        }
    }
}

// ---------------- CSR build ----------------
__global__ void hist_kernel(const int* __restrict__ dst, int* __restrict__ deg, int E)
{
    int i = blockIdx.x * blockDim.x + threadIdx.x;
    if (i < E) atomicAdd(&deg[dst[i]], 1);
}

// writes rowptr[0..N] and cursor[i] = rowptr[i] (exclusive prefix)
__global__ void __launch_bounds__(1024) scan_kernel(const int* __restrict__ deg,
                                                    int* __restrict__ rowptr,
                                                    int* __restrict__ cursor, int N)
{
    __shared__ int sums[32];
    __shared__ int carry;
    int tid = threadIdx.x;
    if (tid == 0) carry = 0;
    __syncthreads();
    for (int base = 0; base < N; base += 1024) {
        int i = base + tid;
        int v = (i < N) ? deg[i] : 0;
        int x = v;
        #pragma unroll
        for (int o = 1; o < 32; o <<= 1) {
            int y = __shfl_up_sync(~0u, x, o);
            if ((tid & 31) >= o) x += y;
        }
        if ((tid & 31) == 31) sums[tid >> 5] = x;
        __syncthreads();
        if (tid < 32) {
            int s = sums[tid];
            #pragma unroll
            for (int o = 1; o < 32; o <<= 1) {
                int y = __shfl_up_sync(~0u, s, o);
                if (tid >= o) s += y;
            }
            sums[tid] = s;
        }
        __syncthreads();
        int incl = x + ((tid >= 32) ? sums[(tid >> 5) - 1] : 0) + carry;
        if (i < N) {
            rowptr[i + 1] = incl;
            cursor[i] = incl - v;   // exclusive prefix = rowptr[i]
        }
        __syncthreads();
        if (tid == 1023) carry = incl;
        __syncthreads();
    }
    if (tid == 0) rowptr[0] = 0;
}

__global__ void scatter_kernel(const int* __restrict__ src, const int* __restrict__ dst,
                               int* __restrict__ cursor, int* __restrict__ col, int E)
{
    int i = blockIdx.x * blockDim.x + threadIdx.x;
    if (i >= E) return;
    int slot = atomicAdd(&cursor[dst[i]], 1);
    col[slot] = src[i];
}

// ---------------- GAT kernels ----------------
__global__ void alpha_kernel(const float* __restrict__ h,
                             const float* __restrict__ a_src,
                             const float* __restrict__ a_dst,
                             float* __restrict__ asrc, float* __restrict__ adst,
                             int N, int H, int C)
{
    int idx = blockIdx.x * blockDim.x + threadIdx.x;
    if (idx >= N * H) return;
    int n = idx / H, hh = idx % H;
    const float* hp = h + (size_t)n * H * C + hh * C;
    const float* as = a_src + hh * C;
    const float* ad = a_dst + hh * C;
    float s1 = 0.f, s2 = 0.f;
    for (int c = 0; c < C; c++) { float v = hp[c]; s1 += v * as[c]; s2 += v * ad[c]; }
    asrc[idx] = s1;
    adst[idx] = s2;
}

// fused softmax + gather aggregation + bias + relu. one warp per (node, head).
template<int H, int CPL>
__global__ void gat_aggregate(const int* __restrict__ rowptr, const int* __restrict__ col,
                              const float* __restrict__ asrc, const float* __restrict__ adst,
                              const float* __restrict__ h, const float* __restrict__ bias,
                              float* __restrict__ out, int N)
{
    const int C = 32 * CPL;
    int warp = (blockIdx.x * blockDim.x + threadIdx.x) >> 5;
    int lane = threadIdx.x & 31;
    if (warp >= N * H) return;
    int d = warp / H, hh = warp % H;
    int beg = rowptr[d], end = rowptr[d + 1];
    float ad = adst[d * H + hh];

    float m = -INFINITY, den = 0.f;
    for (int i = beg + lane; i < end; i += 32) {
        float v = asrc[col[i] * H + hh] + ad;
        v = (v >= 0.f) ? v : 0.2f * v;
        if (v > m) { den = den * expf(m - v) + 1.f; m = v; }
        else den += expf(v - m);
    }
    #pragma unroll
    for (int o = 16; o; o >>= 1) {
        float m2 = __shfl_xor_sync(~0u, m, o);
        float d2 = __shfl_xor_sync(~0u, den, o);
        float nm = fmaxf(m, m2);
        float f1 = (m == nm) ? 1.f : expf(m - nm);
        float f2 = (m2 == nm) ? 1.f : expf(m2 - nm);
        den = den * f1 + d2 * f2;
        m = nm;
    }
    float inv = 1.f / (den + 1e-16f);

    float acc[CPL];
    #pragma unroll
    for (int q = 0; q < CPL; q++) acc[q] = 0.f;

    for (int base = beg; base < end; base += 32) {
        int i = base + lane;
        int s = 0; float coef = 0.f;
        if (i < end) {
            s = col[i];
            float v = asrc[s * H + hh] + ad;
            v = (v >= 0.f) ? v : 0.2f * v;
            coef = expf(v - m) * inv;
        }
        int cnt = min(32, end - base);
        for (int j = 0; j < cnt; j++) {
            int sj = __shfl_sync(~0u, s, j);
            float cj = __shfl_sync(~0u, coef, j);
            const float* hp = h + ((size_t)sj * H + hh) * C + lane * CPL;
            if (CPL == 4) {
                float4 v4 = *(const float4*)hp;
                acc[0] += cj * v4.x; acc[1] += cj * v4.y;
                acc[2] += cj * v4.z; acc[3] += cj * v4.w;
            } else {
                float2 v2 = *(const float2*)hp;
                acc[0] += cj * v2.x; acc[1] += cj * v2.y;
            }
        }
    }

    float* op = out + ((size_t)d * H + hh) * C + lane * CPL;
    const float* bp = bias + hh * C + lane * CPL;
    if (CPL == 4) {
        float4 v;
        v.x = fmaxf(acc[0] + bp[0], 0.f); v.y = fmaxf(acc[1] + bp[1], 0.f);
        v.z = fmaxf(acc[2] + bp[2], 0.f); v.w = fmaxf(acc[3] + bp[3], 0.f);
        *(float4*)op = v;
    } else {
        float2 v;
        v.x = fmaxf(acc[0] + bp[0], 0.f); v.y = fmaxf(acc[1] + bp[1], 0.f);
        *(float2*)op = v;
    }
}

// ================= final GEMM via mma.sync tf32 ============================
// t-major smem layout: elem (row, col) at [row*ASTR + (col&3)*18 + (col>>2)]
#define ASTR 72
__global__ void __launch_bounds__(256) final_mma_kernel(
    const float* __restrict__ A, const float* __restrict__ B, float* __restrict__ C)
{
    __shared__ uint32_t As[128 * ASTR];
    __shared__ uint32_t Bs[128 * ASTR];

    const int tid = threadIdx.x, wid = tid >> 5, lane = tid & 31;
    const int g = lane >> 2, t = lane & 3;
    const int wm = wid & 3, wn = wid >> 2;
    const int m0 = blockIdx.y * 128, n0 = blockIdx.x * 128;

    {
        const float* Ag = A + (size_t)m0 * 64;
        const float* Bg = B + (size_t)n0 * 64;
        #pragma unroll
        for (int i = tid; i < 2048; i += 256) {
            int row = i >> 4, c4 = (i & 15) << 2;
            float4 v = *(const float4*)(Ag + (size_t)row * 64 + c4);
            uint32_t* p = &As[row * ASTR + (c4 >> 2)];
            p[0]  = cvt_tf32(v.x); p[18] = cvt_tf32(v.y);
            p[36] = cvt_tf32(v.z); p[54] = cvt_tf32(v.w);
        }
        #pragma unroll
        for (int i = tid; i < 2048; i += 256) {
            int row = i >> 4, c4 = (i & 15) << 2;
            float4 v = *(const float4*)(Bg + (size_t)row * 64 + c4);
            uint32_t* p = &Bs[row * ASTR + (c4 >> 2)];
            p[0]  = cvt_tf32(v.x); p[18] = cvt_tf32(v.y);
            p[36] = cvt_tf32(v.z); p[54] = cvt_tf32(v.w);
        }
    }
    __syncthreads();

    float acc[2][8][4];
    #pragma unroll
    for (int i = 0; i < 2; i++)
        #pragma unroll
        for (int j = 0; j < 8; j++)
            #pragma unroll
            for (int q = 0; q < 4; q++) acc[i][j][q] = 0.f;

    const int arow = wm * 32;
    const int bcol = wn * 64;
    const int toff = t * 18;

    #pragma unroll
    for (int ks = 0; ks < 8; ks++) {
        const int kb2 = ks * 2;
        uint32_t a[2][4];
        #pragma unroll
        for (int mf = 0; mf < 2; mf++) {
            int r = arow + mf * 16;
            uint2 lo = *(const uint2*)&As[(r + g)     * ASTR + toff + kb2];
            uint2 hi = *(const uint2*)&As[(r + g + 8) * ASTR + toff + kb2];
            a[mf][0] = lo.x; a[mf][2] = lo.y;
            a[mf][1] = hi.x; a[mf][3] = hi.y;
        }
        #pragma unroll
        for (int nf = 0; nf < 8; nf++) {
            int n = bcol + nf * 8 + g;
            uint2 bb = *(const uint2*)&Bs[n * ASTR + toff + kb2];
            uint32_t b[2] = {bb.x, bb.y};
            mma_tf32(acc[0][nf], a[0], b);
            mma_tf32(acc[1][nf], a[1], b);
        }
    }

    #pragma unroll
    for (int mf = 0; mf < 2; mf++) {
        #pragma unroll
        for (int rr = 0; rr < 2; rr++) {
            int row = m0 + arow + mf * 16 + rr * 8 + g;
            if (row >= M_NODES) continue;
            float* cp = C + (size_t)row * D_NODES;
            #pragma unroll
            for (int nf = 0; nf < 8; nf++) {
                int col = n0 + bcol + nf * 8 + 2 * t;
                if (col + 1 < D_NODES) {
                    float2 v;
                    v.x = acc[mf][nf][rr * 2 + 0];
                    v.y = acc[mf][nf][rr * 2 + 1];
                    *(float2*)(cp + col) = v;
                } else if (col < D_NODES) {
                    cp[col] = acc[mf][nf][rr * 2 + 0];
                }
            }
        }
    }
}

// ---------------- host orchestration ----------------
static void run_gemm(const float* A, const float* B, const float* bias, float* C,
                     int N, int K, int Cn, int act, cudaStream_t st)
{
    dim3 g(Cn / 64, (N + 127) / 128);
    mma_gemm_kernel<<<g, 256, 0, st>>>(A, B, bias, C, N, K, Cn, act);
}

static void build_csr(const int* ei, int E, int N, int* rowptr, int* col,
                      int* cursor, int* deg, cudaStream_t st)
{
    const int* src = ei;
    const int* dst = ei + E;
    cudaMemsetAsync(deg, 0, N * sizeof(int), st);
    hist_kernel<<<(E + 255) / 256, 256, 0, st>>>(dst, deg, E);
    scan_kernel<<<1, 1024, 0, st>>>(deg, rowptr, cursor, N);
    scatter_kernel<<<(E + 255) / 256, 256, 0, st>>>(src, dst, cursor, col, E);
}

extern "C" void kernel_launch(void* const* d_in, const int* in_sizes, int n_in,
                              void* d_out, int out_size)
{
    const float* x_m  = (const float*)d_in[0];
    const float* x_d  = (const float*)d_in[1];
    const int*   mm   = (const int*)d_in[2];
    const int*   dd   = (const int*)d_in[3];
    const float* W_gx1 = (const float*)d_in[4];
    const float* as_gx1 = (const float*)d_in[5];
    const float* ad_gx1 = (const float*)d_in[6];
    const float* b_gx1  = (const float*)d_in[7];
    const float* W_gx2 = (const float*)d_in[8];
    const float* as_gx2 = (const float*)d_in[9];
    const float* ad_gx2 = (const float*)d_in[10];
    const float* b_gx2  = (const float*)d_in[11];
    const float* W_gy1 = (const float*)d_in[12];
    const float* as_gy1 = (const float*)d_in[13];
    const float* ad_gy1 = (const float*)d_in[14];
    const float* b_gy1  = (const float*)d_in[15];
    const float* W_gy2 = (const float*)d_in[16];
    const float* as_gy2 = (const float*)d_in[17];
    const float* ad_gy2 = (const float*)d_in[18];
    const float* b_gy2  = (const float*)d_in[19];
    const float* lx1_W = (const float*)d_in[20];
    const float* lx1_b = (const float*)d_in[21];
    const float* lx2_W = (const float*)d_in[22];
    const float* lx2_b = (const float*)d_in[23];
    const float* lx3_W = (const float*)d_in[24];
    const float* lx3_b = (const float*)d_in[25];
    const float* ly1_W = (const float*)d_in[26];
    const float* ly1_b = (const float*)d_in[27];
    const float* ly2_W = (const float*)d_in[28];
    const float* ly2_b = (const float*)d_in[29];
    const float* ly3_W = (const float*)d_in[30];
    const float* ly3_b = (const float*)d_in[31];

    float *h, *feat, *asrc, *adst, *X, *t1, *t2, *xf;
    float *hY, *featY, *asrcY, *adstY, *XY, *t1Y, *t2Y, *yf;
    int *rpA, *colA, *curA, *degA, *rpB, *colB, *curB, *degB;
    cudaGetSymbolAddress((void**)&h,    g_h);
    cudaGetSymbolAddress((void**)&feat, g_feat);
    cudaGetSymbolAddress((void**)&asrc, g_asrc);
    cudaGetSymbolAddress((void**)&adst, g_adst);
    cudaGetSymbolAddress((void**)&X,    g_X);
    cudaGetSymbolAddress((void**)&t1,   g_t1);
    cudaGetSymbolAddress((void**)&t2,   g_t2);
    cudaGetSymbolAddress((void**)&xf,   g_xf);
    cudaGetSymbolAddress((void**)&rpA,  g_rpA);
    cudaGetSymbolAddress((void**)&colA, g_colA);
    cudaGetSymbolAddress((void**)&curA, g_curA);
    cudaGetSymbolAddress((void**)&degA, g_degA);
    cudaGetSymbolAddress((void**)&hY,    g_hY);
    cudaGetSymbolAddress((void**)&featY, g_featY);
    cudaGetSymbolAddress((void**)&asrcY, g_asrcY);
    cudaGetSymbolAddress((void**)&adstY, g_adstY);
    cudaGetSymbolAddress((void**)&XY,    g_XY);
    cudaGetSymbolAddress((void**)&t1Y,   g_t1Y);
    cudaGetSymbolAddress((void**)&t2Y,   g_t2Y);
    cudaGetSymbolAddress((void**)&yf,    g_yf);
    cudaGetSymbolAddress((void**)&rpB,  g_rpB);
    cudaGetSymbolAddress((void**)&colB, g_colB);
    cudaGetSymbolAddress((void**)&curB, g_curB);
    cudaGetSymbolAddress((void**)&degB, g_degB);

    // maximize smem carveout so multi-CTA residency isn't capped by default L1 split
    cudaFuncSetAttribute(final_mma_kernel, cudaFuncAttributePreferredSharedMemoryCarveout, 100);
    cudaFuncSetAttribute(mma_gemm_kernel,  cudaFuncAttributePreferredSharedMemoryCarveout, 100);

    // fork: sY = Y branch, sC = X CSR build (both capture-safe fork/join)
    static cudaStream_t sY = 0, sC = 0;
    static cudaEvent_t eFork = 0, eJoin = 0, eCsr = 0;
    static bool inited = false, forked = false;
    if (!inited) {
        inited = true;
        forked = (cudaStreamCreateWithFlags(&sY, cudaStreamNonBlocking) == cudaSuccess)
              && (cudaStreamCreateWithFlags(&sC, cudaStreamNonBlocking) == cudaSuccess)
              && (cudaEventCreateWithFlags(&eFork, cudaEventDisableTiming) == cudaSuccess)
              && (cudaEventCreateWithFlags(&eJoin, cudaEventDisableTiming) == cudaSuccess)
              && (cudaEventCreateWithFlags(&eCsr,  cudaEventDisableTiming) == cudaSuccess);
    }
    cudaStream_t sy = forked ? sY : 0;
    cudaStream_t sc = forked ? sC : 0;
    if (forked) {
        cudaEventRecord(eFork, 0);
        cudaStreamWaitEvent(sY, eFork, 0);
        cudaStreamWaitEvent(sC, eFork, 0);
    }

    // ----- X CSR build (side stream sc, overlaps X projection) -----
    build_csr(mm, E_MM, M_NODES, rpA, colA, curA, degA, sc);
    if (forked) cudaEventRecord(eCsr, sC);

    // ----- X branch (stream 0) -----
    cudaMemsetAsync(xf + (size_t)M_NODES * 64, 0, (size_t)(MPAD - M_NODES) * 64 * sizeof(float), 0);
    // GAT layer 1: projection + alpha don't need CSR
    run_gemm(x_m, W_gx1, nullptr, h, M_NODES, 64, 256, 0, 0);
    alpha_kernel<<<(M_NODES * 2 + 255) / 256, 256, 0, 0>>>(h, as_gx1, ad_gx1, asrc, adst, M_NODES, 2, 128);
    if (forked) cudaStreamWaitEvent(0, eCsr, 0);
    gat_aggregate<2, 4><<<(M_NODES * 2 + 7) / 8, 256, 0, 0>>>(rpA, colA, asrc, adst, h, b_gx1, feat, M_NODES);
    // GAT layer 2
    run_gemm(feat, W_gx2, nullptr, h, M_NODES, 256, 64, 0, 0);
    alpha_kernel<<<(M_NODES + 255) / 256, 256, 0, 0>>>(h, as_gx2, ad_gx2, asrc, adst, M_NODES, 1, 64);
    gat_aggregate<1, 2><<<(M_NODES + 7) / 8, 256, 0, 0>>>(rpA, colA, asrc, adst, h, b_gx2, X, M_NODES);
    // MLP
    run_gemm(X,  lx1_W, lx1_b, t1, M_NODES, 64,  256, 1, 0);
    run_gemm(t1, lx2_W, lx2_b, t2, M_NODES, 256, 128, 1, 0);
    run_gemm(t2, lx3_W, lx3_b, xf, M_NODES, 128, 64,  1, 0);

    // ----- Y branch (side stream sy) -----
    cudaMemsetAsync(yf + (size_t)D_NODES * 64, 0, (size_t)(DPAD - D_NODES) * 64 * sizeof(float), sy);
    build_csr(dd, E_DD, D_NODES, rpB, colB, curB, degB, sy);
    run_gemm(x_d, W_gy1, nullptr, hY, D_NODES, 64, 256, 0, sy);
    alpha_kernel<<<(D_NODES * 2 + 255) / 256, 256, 0, sy>>>(hY, as_gy1, ad_gy1, asrcY, adstY, D_NODES, 2, 128);
    gat_aggregate<2, 4><<<(D_NODES * 2 + 7) / 8, 256, 0, sy>>>(rpB, colB, asrcY, adstY, hY, b_gy1, featY, D_NODES);
    run_gemm(featY, W_gy2, nullptr, hY, D_NODES, 256, 64, 0, sy);
    alpha_kernel<<<(D_NODES + 255) / 256, 256, 0, sy>>>(hY, as_gy2, ad_gy2, asrcY, adstY, D_NODES, 1, 64);
    gat_aggregate<1, 2><<<(D_NODES + 7) / 8, 256, 0, sy>>>(rpB, colB, asrcY, adstY, hY, b_gy2, XY, D_NODES);
    run_gemm(XY,  ly1_W, ly1_b, t1Y, D_NODES, 64,  256, 1, sy);
    run_gemm(t1Y, ly2_W, ly2_b, t2Y, D_NODES, 256, 128, 1, sy);
    run_gemm(t2Y, ly3_W, ly3_b, yf,  D_NODES, 128, 64,  1, sy);

    if (forked) {
        cudaEventRecord(eJoin, sY);
        cudaStreamWaitEvent(0, eJoin, 0);
    }

    // ----- final: out = xf @ yf^T (stream 0) -----
    dim3 grid(DPAD / 128, MPAD / 128);
    final_mma_kernel<<<grid, 256, 0, 0>>>(xf, yf, (float*)d_out);
}

// round 8
// speedup vs baseline: 3.8448x; 1.0039x over previous
#include <cuda_runtime.h>
#include <math.h>
#include <stdint.h>

// ---------------- problem constants ----------------
#define M_NODES 20000
#define D_NODES 8000
#define E_MM    320000
#define E_DD    128000

#define MPAD 20096   // 157 * 128
#define DPAD 8064    // 63  * 128

// ---------------- scratch (device globals; allocation-free) ----------------
__device__ float    g_h   [M_NODES * 256];
__device__ float    g_feat[M_NODES * 256];
__device__ float    g_asrc[M_NODES * 2];
__device__ float    g_adst[M_NODES * 2];
__device__ float    g_X   [M_NODES * 64];
__device__ float    g_t1  [M_NODES * 256];
__device__ float    g_t2  [M_NODES * 128];
__device__ float    g_xf  [MPAD * 64];
__device__ int      g_rpA [M_NODES + 1];
__device__ int      g_colA[E_MM];
__device__ int      g_curA[M_NODES];
__device__ int      g_degA[M_NODES];
__device__ float    g_hY   [D_NODES * 256];
__device__ float    g_featY[D_NODES * 256];
__device__ float    g_asrcY[D_NODES * 2];
__device__ float    g_adstY[D_NODES * 2];
__device__ float    g_XY   [D_NODES * 64];
__device__ float    g_t1Y  [D_NODES * 256];
__device__ float    g_t2Y  [D_NODES * 128];
__device__ float    g_yf   [DPAD * 64];
__device__ int      g_rpB  [D_NODES + 1];
__device__ int      g_colB [E_DD];
__device__ int      g_curB [D_NODES];
__device__ int      g_degB [D_NODES];

// ---------------- helpers ----------------
__device__ __forceinline__ uint32_t cvt_tf32(float f) {
    uint32_t r;
    asm("cvt.rna.tf32.f32 %0, %1;" : "=r"(r) : "f"(f));
    return r;
}
__device__ __forceinline__ void mma_tf32(float* d, const uint32_t* a, const uint32_t* b)
{
    asm volatile(
        "mma.sync.aligned.m16n8k8.row.col.f32.tf32.tf32.f32 "
        "{%0,%1,%2,%3}, {%4,%5,%6,%7}, {%8,%9}, {%0,%1,%2,%3};"
        : "+f"(d[0]), "+f"(d[1]), "+f"(d[2]), "+f"(d[3])
        : "r"(a[0]), "r"(a[1]), "r"(a[2]), "r"(a[3]), "r"(b[0]), "r"(b[1]));
}

// ============ generic tf32 mma GEMM: C = act(A[N,K] @ B[K,Cn] + bias) ======
#define GSTR 68
__global__ void __launch_bounds__(256) mma_gemm_kernel(
    const float* __restrict__ A, const float* __restrict__ B,
    const float* __restrict__ bias, float* __restrict__ C,
    int N, int K, int Cn, int relu_act)
{
    __shared__ uint32_t As[128 * GSTR];
    __shared__ uint32_t Bs[64 * GSTR];

    const int tid = threadIdx.x, wid = tid >> 5, lane = tid & 31;
    const int g = lane >> 2, t = lane & 3;
    const int wm = wid & 3, wn = wid >> 2;
    const int row0 = blockIdx.y * 128, col0 = blockIdx.x * 64;

    float acc[2][4][4];
    #pragma unroll
    for (int i = 0; i < 2; i++)
        #pragma unroll
        for (int j = 0; j < 4; j++)
            #pragma unroll
            for (int q = 0; q < 4; q++) acc[i][j][q] = 0.f;

    for (int k0 = 0; k0 < K; k0 += 64) {
        #pragma unroll
        for (int i = tid; i < 2048; i += 256) {
            int row = i >> 4, c4 = (i & 15) << 2;
            int gm = row0 + row;
            float4 v = make_float4(0.f, 0.f, 0.f, 0.f);
            if (gm < N) v = *(const float4*)(A + (size_t)gm * K + k0 + c4);
            uint32_t* p = &As[row * GSTR + c4];
            p[0] = cvt_tf32(v.x); p[1] = cvt_tf32(v.y);
            p[2] = cvt_tf32(v.z); p[3] = cvt_tf32(v.w);
        }
        #pragma unroll
        for (int i = tid; i < 1024; i += 256) {
            int kk = i >> 4, c4 = (i & 15) << 2;
            float4 v = *(const float4*)(B + (size_t)(k0 + kk) * Cn + col0 + c4);
            Bs[(c4 + 0) * GSTR + kk] = cvt_tf32(v.x);
            Bs[(c4 + 1) * GSTR + kk] = cvt_tf32(v.y);
            Bs[(c4 + 2) * GSTR + kk] = cvt_tf32(v.z);
            Bs[(c4 + 3) * GSTR + kk] = cvt_tf32(v.w);
        }
        __syncthreads();

        #pragma unroll
        for (int ks = 0; ks < 8; ks++) {
            const int kb = ks * 8;
            uint32_t a[2][4];
            #pragma unroll
            for (int mf = 0; mf < 2; mf++) {
                int r = wm * 32 + mf * 16;
                a[mf][0] = As[(r + g)     * GSTR + kb + t];
                a[mf][1] = As[(r + g + 8) * GSTR + kb + t];
                a[mf][2] = As[(r + g)     * GSTR + kb + t + 4];
                a[mf][3] = As[(r + g + 8) * GSTR + kb + t + 4];
            }
            #pragma unroll
            for (int nf = 0; nf < 4; nf++) {
                uint32_t b[2];
                int n = wn * 32 + nf * 8 + g;
                b[0] = Bs[n * GSTR + kb + t];
                b[1] = Bs[n * GSTR + kb + t + 4];
                mma_tf32(acc[0][nf], a[0], b);
                mma_tf32(acc[1][nf], a[1], b);
            }
        }
        __syncthreads();
    }

    #pragma unroll
    for (int mf = 0; mf < 2; mf++) {
        #pragma unroll
        for (int rr = 0; rr < 2; rr++) {
            int row = row0 + wm * 32 + mf * 16 + rr * 8 + g;
            if (row >= N) continue;
            float* cp = C + (size_t)row * Cn;
            #pragma unroll
            for (int nf = 0; nf < 4; nf++) {
                int col = col0 + wn * 32 + nf * 8 + 2 * t;
                float2 v;
                v.x = acc[mf][nf][rr * 2 + 0];
                v.y = acc[mf][nf][rr * 2 + 1];
                if (bias) { v.x += bias[col]; v.y += bias[col + 1]; }
                if (relu_act) { v.x = fmaxf(v.x, 0.f); v.y = fmaxf(v.y, 0.f); }
                *(float2*)(cp + col) = v;
            }
        }
    }
}

// ---------------- CSR build ----------------
__global__ void hist_kernel(const int* __restrict__ dst, int* __restrict__ deg, int E)
{
    int i = blockIdx.x * blockDim.x + threadIdx.x;
    if (i < E) atomicAdd(&deg[dst[i]], 1);
}

__global__ void __launch_bounds__(1024) scan_kernel(const int* __restrict__ deg,
                                                    int* __restrict__ rowptr,
                                                    int* __restrict__ cursor, int N)
{
    __shared__ int sums[32];
    __shared__ int carry;
    int tid = threadIdx.x;
    if (tid == 0) carry = 0;
    __syncthreads();
    for (int base = 0; base < N; base += 1024) {
        int i = base + tid;
        int v = (i < N) ? deg[i] : 0;
        int x = v;
        #pragma unroll
        for (int o = 1; o < 32; o <<= 1) {
            int y = __shfl_up_sync(~0u, x, o);
            if ((tid & 31) >= o) x += y;
        }
        if ((tid & 31) == 31) sums[tid >> 5] = x;
        __syncthreads();
        if (tid < 32) {
            int s = sums[tid];
            #pragma unroll
            for (int o = 1; o < 32; o <<= 1) {
                int y = __shfl_up_sync(~0u, s, o);
                if (tid >= o) s += y;
            }
            sums[tid] = s;
        }
        __syncthreads();
        int incl = x + ((tid >= 32) ? sums[(tid >> 5) - 1] : 0) + carry;
        if (i < N) {
            rowptr[i + 1] = incl;
            cursor[i] = incl - v;
        }
        __syncthreads();
        if (tid == 1023) carry = incl;
        __syncthreads();
    }
    if (tid == 0) rowptr[0] = 0;
}

__global__ void scatter_kernel(const int* __restrict__ src, const int* __restrict__ dst,
                               int* __restrict__ cursor, int* __restrict__ col, int E)
{
    int i = blockIdx.x * blockDim.x + threadIdx.x;
    if (i >= E) return;
    int slot = atomicAdd(&cursor[dst[i]], 1);
    col[slot] = src[i];
}

// ---------------- GAT kernels ----------------
__global__ void alpha_kernel(const float* __restrict__ h,
                             const float* __restrict__ a_src,
                             const float* __restrict__ a_dst,
                             float* __restrict__ asrc, float* __restrict__ adst,
                             int N, int H, int C)
{
    int idx = blockIdx.x * blockDim.x + threadIdx.x;
    if (idx >= N * H) return;
    int n = idx / H, hh = idx % H;
    const float* hp = h + (size_t)n * H * C + hh * C;
    const float* as = a_src + hh * C;
    const float* ad = a_dst + hh * C;
    float s1 = 0.f, s2 = 0.f;
    for (int c = 0; c < C; c++) { float v = hp[c]; s1 += v * as[c]; s2 += v * ad[c]; }
    asrc[idx] = s1;
    adst[idx] = s2;
}

template<int H, int CPL>
__global__ void gat_aggregate(const int* __restrict__ rowptr, const int* __restrict__ col,
                              const float* __restrict__ asrc, const float* __restrict__ adst,
                              const float* __restrict__ h, const float* __restrict__ bias,
                              float* __restrict__ out, int N)
{
    const int C = 32 * CPL;
    int warp = (blockIdx.x * blockDim.x + threadIdx.x) >> 5;
    int lane = threadIdx.x & 31;
    if (warp >= N * H) return;
    int d = warp / H, hh = warp % H;
    int beg = rowptr[d], end = rowptr[d + 1];
    float ad = adst[d * H + hh];

    float m = -INFINITY, den = 0.f;
    for (int i = beg + lane; i < end; i += 32) {
        float v = asrc[col[i] * H + hh] + ad;
        v = (v >= 0.f) ? v : 0.2f * v;
        if (v > m) { den = den * expf(m - v) + 1.f; m = v; }
        else den += expf(v - m);
    }
    #pragma unroll
    for (int o = 16; o; o >>= 1) {
        float m2 = __shfl_xor_sync(~0u, m, o);
        float d2 = __shfl_xor_sync(~0u, den, o);
        float nm = fmaxf(m, m2);
        float f1 = (m == nm) ? 1.f : expf(m - nm);
        float f2 = (m2 == nm) ? 1.f : expf(m2 - nm);
        den = den * f1 + d2 * f2;
        m = nm;
    }
    float inv = 1.f / (den + 1e-16f);

    float acc[CPL];
    #pragma unroll
    for (int q = 0; q < CPL; q++) acc[q] = 0.f;

    for (int base = beg; base < end; base += 32) {
        int i = base + lane;
        int s = 0; float coef = 0.f;
        if (i < end) {
            s = col[i];
            float v = asrc[s * H + hh] + ad;
            v = (v >= 0.f) ? v : 0.2f * v;
            coef = expf(v - m) * inv;
        }
        int cnt = min(32, end - base);
        for (int j = 0; j < cnt; j++) {
            int sj = __shfl_sync(~0u, s, j);
            float cj = __shfl_sync(~0u, coef, j);
            const float* hp = h + ((size_t)sj * H + hh) * C + lane * CPL;
            if (CPL == 4) {
                float4 v4 = *(const float4*)hp;
                acc[0] += cj * v4.x; acc[1] += cj * v4.y;
                acc[2] += cj * v4.z; acc[3] += cj * v4.w;
            } else {
                float2 v2 = *(const float2*)hp;
                acc[0] += cj * v2.x; acc[1] += cj * v2.y;
            }
        }
    }

    float* op = out + ((size_t)d * H + hh) * C + lane * CPL;
    const float* bp = bias + hh * C + lane * CPL;
    if (CPL == 4) {
        float4 v;
        v.x = fmaxf(acc[0] + bp[0], 0.f); v.y = fmaxf(acc[1] + bp[1], 0.f);
        v.z = fmaxf(acc[2] + bp[2], 0.f); v.w = fmaxf(acc[3] + bp[3], 0.f);
        *(float4*)op = v;
    } else {
        float2 v;
        v.x = fmaxf(acc[0] + bp[0], 0.f); v.y = fmaxf(acc[1] + bp[1], 0.f);
        *(float2*)op = v;
    }
}

// ================= final GEMM via mma.sync tf32 ============================
// mainloop smem: t-major, elem (row,col) at [row*ASTR + (col&3)*18 + (col>>2)]
// epilogue: stage 128x128 f32 tile in (reused) smem, store coalesced float4.
#define ASTR 72
#define CSTR 132   // stage stride in floats (mult of 4 for LDS.128)

__global__ void __launch_bounds__(256) final_mma_kernel(
    const float* __restrict__ A, const float* __restrict__ B, float* __restrict__ C)
{
    __shared__ uint32_t SM[2 * 128 * ASTR];   // 73.7 KB; stage needs 128*132*4=67.6 KB
    uint32_t* As = SM;
    uint32_t* Bs = SM + 128 * ASTR;

    const int tid = threadIdx.x, wid = tid >> 5, lane = tid & 31;
    const int g = lane >> 2, t = lane & 3;
    const int wm = wid & 3, wn = wid >> 2;
    const int m0 = blockIdx.y * 128, n0 = blockIdx.x * 128;

    {
        const float* Ag = A + (size_t)m0 * 64;
        const float* Bg = B + (size_t)n0 * 64;
        #pragma unroll
        for (int i = tid; i < 2048; i += 256) {
            int row = i >> 4, c4 = (i & 15) << 2;
            float4 v = *(const float4*)(Ag + (size_t)row * 64 + c4);
            uint32_t* p = &As[row * ASTR + (c4 >> 2)];
            p[0]  = cvt_tf32(v.x); p[18] = cvt_tf32(v.y);
            p[36] = cvt_tf32(v.z); p[54] = cvt_tf32(v.w);
        }
        #pragma unroll
        for (int i = tid; i < 2048; i += 256) {
            int row = i >> 4, c4 = (i & 15) << 2;
            float4 v = *(const float4*)(Bg + (size_t)row * 64 + c4);
            uint32_t* p = &Bs[row * ASTR + (c4 >> 2)];
            p[0]  = cvt_tf32(v.x); p[18] = cvt_tf32(v.y);
            p[36] = cvt_tf32(v.z); p[54] = cvt_tf32(v.w);
        }
    }
    __syncthreads();

    float acc[2][8][4];
    #pragma unroll
    for (int i = 0; i < 2; i++)
        #pragma unroll
        for (int j = 0; j < 8; j++)
            #pragma unroll
            for (int q = 0; q < 4; q++) acc[i][j][q] = 0.f;

    const int arow = wm * 32;
    const int bcol = wn * 64;
    const int toff = t * 18;

    #pragma unroll
    for (int ks = 0; ks < 8; ks++) {
        const int kb2 = ks * 2;
        uint32_t a[2][4];
        #pragma unroll
        for (int mf = 0; mf < 2; mf++) {
            int r = arow + mf * 16;
            uint2 lo = *(const uint2*)&As[(r + g)     * ASTR + toff + kb2];
            uint2 hi = *(const uint2*)&As[(r + g + 8) * ASTR + toff + kb2];
            a[mf][0] = lo.x; a[mf][2] = lo.y;
            a[mf][1] = hi.x; a[mf][3] = hi.y;
        }
        #pragma unroll
        for (int nf = 0; nf < 8; nf++) {
            int n = bcol + nf * 8 + g;
            uint2 bb = *(const uint2*)&Bs[n * ASTR + toff + kb2];
            uint32_t b[2] = {bb.x, bb.y};
            mma_tf32(acc[0][nf], a[0], b);
            mma_tf32(acc[1][nf], a[1], b);
        }
    }

    // ---- epilogue: stage to smem, then coalesced float4 stores ----
    __syncthreads();                       // all LDS from As/Bs done
    float* stage = (float*)SM;
    #pragma unroll
    for (int mf = 0; mf < 2; mf++) {
        #pragma unroll
        for (int rr = 0; rr < 2; rr++) {
            int rloc = arow + mf * 16 + rr * 8 + g;
            #pragma unroll
            for (int nf = 0; nf < 8; nf++) {
                int cloc = bcol + nf * 8 + 2 * t;
                float2 v;
                v.x = acc[mf][nf][rr * 2 + 0];
                v.y = acc[mf][nf][rr * 2 + 1];
                *(float2*)&stage[rloc * CSTR + cloc] = v;
            }
        }
    }
    __syncthreads();

    // 128 rows x 128 cols; each iteration: one warp = one row (32 x float4)
    #pragma unroll
    for (int i = tid; i < 128 * 32; i += 256) {
        int rloc = i >> 5, c4 = (i & 31) << 2;
        int row = m0 + rloc;
        if (row >= M_NODES) continue;
        int col = n0 + c4;
        float4 v = *(const float4*)&stage[rloc * CSTR + c4];
        if (col + 3 < D_NODES) {
            *(float4*)(C + (size_t)row * D_NODES + col) = v;
        } else {
            float vv[4] = {v.x, v.y, v.z, v.w};
            #pragma unroll
            for (int q = 0; q < 4; q++)
                if (col + q < D_NODES) C[(size_t)row * D_NODES + col + q] = vv[q];
        }
    }
}

// ---------------- host orchestration ----------------
static void run_gemm(const float* A, const float* B, const float* bias, float* C,
                     int N, int K, int Cn, int act, cudaStream_t st)
{
    dim3 g(Cn / 64, (N + 127) / 128);
    mma_gemm_kernel<<<g, 256, 0, st>>>(A, B, bias, C, N, K, Cn, act);
}

static void build_csr(const int* ei, int E, int N, int* rowptr, int* col,
                      int* cursor, int* deg, cudaStream_t st)
{
    const int* src = ei;
    const int* dst = ei + E;
    cudaMemsetAsync(deg, 0, N * sizeof(int), st);
    hist_kernel<<<(E + 255) / 256, 256, 0, st>>>(dst, deg, E);
    scan_kernel<<<1, 1024, 0, st>>>(deg, rowptr, cursor, N);
    scatter_kernel<<<(E + 255) / 256, 256, 0, st>>>(src, dst, cursor, col, E);
}

extern "C" void kernel_launch(void* const* d_in, const int* in_sizes, int n_in,
                              void* d_out, int out_size)
{
    const float* x_m  = (const float*)d_in[0];
    const float* x_d  = (const float*)d_in[1];
    const int*   mm   = (const int*)d_in[2];
    const int*   dd   = (const int*)d_in[3];
    const float* W_gx1 = (const float*)d_in[4];
    const float* as_gx1 = (const float*)d_in[5];
    const float* ad_gx1 = (const float*)d_in[6];
    const float* b_gx1  = (const float*)d_in[7];
    const float* W_gx2 = (const float*)d_in[8];
    const float* as_gx2 = (const float*)d_in[9];
    const float* ad_gx2 = (const float*)d_in[10];
    const float* b_gx2  = (const float*)d_in[11];
    const float* W_gy1 = (const float*)d_in[12];
    const float* as_gy1 = (const float*)d_in[13];
    const float* ad_gy1 = (const float*)d_in[14];
    const float* b_gy1  = (const float*)d_in[15];
    const float* W_gy2 = (const float*)d_in[16];
    const float* as_gy2 = (const float*)d_in[17];
    const float* ad_gy2 = (const float*)d_in[18];
    const float* b_gy2  = (const float*)d_in[19];
    const float* lx1_W = (const float*)d_in[20];
    const float* lx1_b = (const float*)d_in[21];
    const float* lx2_W = (const float*)d_in[22];
    const float* lx2_b = (const float*)d_in[23];
    const float* lx3_W = (const float*)d_in[24];
    const float* lx3_b = (const float*)d_in[25];
    const float* ly1_W = (const float*)d_in[26];
    const float* ly1_b = (const float*)d_in[27];
    const float* ly2_W = (const float*)d_in[28];
    const float* ly2_b = (const float*)d_in[29];
    const float* ly3_W = (const float*)d_in[30];
    const float* ly3_b = (const float*)d_in[31];

    float *h, *feat, *asrc, *adst, *X, *t1, *t2, *xf;
    float *hY, *featY, *asrcY, *adstY, *XY, *t1Y, *t2Y, *yf;
    int *rpA, *colA, *curA, *degA, *rpB, *colB, *curB, *degB;
    cudaGetSymbolAddress((void**)&h,    g_h);
    cudaGetSymbolAddress((void**)&feat, g_feat);
    cudaGetSymbolAddress((void**)&asrc, g_asrc);
    cudaGetSymbolAddress((void**)&adst, g_adst);
    cudaGetSymbolAddress((void**)&X,    g_X);
    cudaGetSymbolAddress((void**)&t1,   g_t1);
    cudaGetSymbolAddress((void**)&t2,   g_t2);
    cudaGetSymbolAddress((void**)&xf,   g_xf);
    cudaGetSymbolAddress((void**)&rpA,  g_rpA);
    cudaGetSymbolAddress((void**)&colA, g_colA);
    cudaGetSymbolAddress((void**)&curA, g_curA);
    cudaGetSymbolAddress((void**)&degA, g_degA);
    cudaGetSymbolAddress((void**)&hY,    g_hY);
    cudaGetSymbolAddress((void**)&featY, g_featY);
    cudaGetSymbolAddress((void**)&asrcY, g_asrcY);
    cudaGetSymbolAddress((void**)&adstY, g_adstY);
    cudaGetSymbolAddress((void**)&XY,    g_XY);
    cudaGetSymbolAddress((void**)&t1Y,   g_t1Y);
    cudaGetSymbolAddress((void**)&t2Y,   g_t2Y);
    cudaGetSymbolAddress((void**)&yf,    g_yf);
    cudaGetSymbolAddress((void**)&rpB,  g_rpB);
    cudaGetSymbolAddress((void**)&colB, g_colB);
    cudaGetSymbolAddress((void**)&curB, g_curB);
    cudaGetSymbolAddress((void**)&degB, g_degB);

    // fork: sY = Y branch, sC = X CSR build
    static cudaStream_t sY = 0, sC = 0;
    static cudaEvent_t eFork = 0, eJoin = 0, eCsr = 0;
    static bool inited = false, forked = false;
    if (!inited) {
        inited = true;
        forked = (cudaStreamCreateWithFlags(&sY, cudaStreamNonBlocking) == cudaSuccess)
              && (cudaStreamCreateWithFlags(&sC, cudaStreamNonBlocking) == cudaSuccess)
              && (cudaEventCreateWithFlags(&eFork, cudaEventDisableTiming) == cudaSuccess)
              && (cudaEventCreateWithFlags(&eJoin, cudaEventDisableTiming) == cudaSuccess)
              && (cudaEventCreateWithFlags(&eCsr,  cudaEventDisableTiming) == cudaSuccess);
    }
    cudaStream_t sy = forked ? sY : 0;
    cudaStream_t sc = forked ? sC : 0;
    if (forked) {
        cudaEventRecord(eFork, 0);
        cudaStreamWaitEvent(sY, eFork, 0);
        cudaStreamWaitEvent(sC, eFork, 0);
    }

    // ----- X CSR build (side stream sc) -----
    build_csr(mm, E_MM, M_NODES, rpA, colA, curA, degA, sc);
    if (forked) cudaEventRecord(eCsr, sC);

    // ----- X branch (stream 0) -----
    cudaMemsetAsync(xf + (size_t)M_NODES * 64, 0, (size_t)(MPAD - M_NODES) * 64 * sizeof(float), 0);
    run_gemm(x_m, W_gx1, nullptr, h, M_NODES, 64, 256, 0, 0);
    alpha_kernel<<<(M_NODES * 2 + 255) / 256, 256, 0, 0>>>(h, as_gx1, ad_gx1, asrc, adst, M_NODES, 2, 128);
    if (forked) cudaStreamWaitEvent(0, eCsr, 0);
    gat_aggregate<2, 4><<<(M_NODES * 2 + 7) / 8, 256, 0, 0>>>(rpA, colA, asrc, adst, h, b_gx1, feat, M_NODES);
    run_gemm(feat, W_gx2, nullptr, h, M_NODES, 256, 64, 0, 0);
    alpha_kernel<<<(M_NODES + 255) / 256, 256, 0, 0>>>(h, as_gx2, ad_gx2, asrc, adst, M_NODES, 1, 64);
    gat_aggregate<1, 2><<<(M_NODES + 7) / 8, 256, 0, 0>>>(rpA, colA, asrc, adst, h, b_gx2, X, M_NODES);
    run_gemm(X,  lx1_W, lx1_b, t1, M_NODES, 64,  256, 1, 0);
    run_gemm(t1, lx2_W, lx2_b, t2, M_NODES, 256, 128, 1, 0);
    run_gemm(t2, lx3_W, lx3_b, xf, M_NODES, 128, 64,  1, 0);

    // ----- Y branch (side stream sy) -----
    cudaMemsetAsync(yf + (size_t)D_NODES * 64, 0, (size_t)(DPAD - D_NODES) * 64 * sizeof(float), sy);
    build_csr(dd, E_DD, D_NODES, rpB, colB, curB, degB, sy);
    run_gemm(x_d, W_gy1, nullptr, hY, D_NODES, 64, 256, 0, sy);
    alpha_kernel<<<(D_NODES * 2 + 255) / 256, 256, 0, sy>>>(hY, as_gy1, ad_gy1, asrcY, adstY, D_NODES, 2, 128);
    gat_aggregate<2, 4><<<(D_NODES * 2 + 7) / 8, 256, 0, sy>>>(rpB, colB, asrcY, adstY, hY, b_gy1, featY, D_NODES);
    run_gemm(featY, W_gy2, nullptr, hY, D_NODES, 256, 64, 0, sy);
    alpha_kernel<<<(D_NODES + 255) / 256, 256, 0, sy>>>(hY, as_gy2, ad_gy2, asrcY, adstY, D_NODES, 1, 64);
    gat_aggregate<1, 2><<<(D_NODES + 7) / 8, 256, 0, sy>>>(rpB, colB, asrcY, adstY, hY, b_gy2, XY, D_NODES);
    run_gemm(XY,  ly1_W, ly1_b, t1Y, D_NODES, 64,  256, 1, sy);
    run_gemm(t1Y, ly2_W, ly2_b, t2Y, D_NODES, 256, 128, 1, sy);
    run_gemm(t2Y, ly3_W, ly3_b, yf,  D_NODES, 128, 64,  1, sy);

    if (forked) {
        cudaEventRecord(eJoin, sY);
        cudaStreamWaitEvent(0, eJoin, 0);
    }

    // ----- final: out = xf @ yf^T (stream 0) -----
    dim3 grid(DPAD / 128, MPAD / 128);
    final_mma_kernel<<<grid, 256, 0, 0>>>(xf, yf, (float*)d_out);
}